// round 3
// baseline (speedup 1.0000x reference)
#include <cuda_runtime.h>
#include <cstdint>

// ---------------------------------------------------------------------------
// MemoryAttention R3: crossbar-traffic-optimal register blocking.
//   8q x 8c per thread (0.125 LDS-bytes/FMA2, half of R2), QT=64 queries/CTA,
//   CT=256 centers/chunk, 1 CTA/SM (grid 128). Top-k candidates in smem,
//   only the per-query threshold lives in registers.
// ---------------------------------------------------------------------------

#define FULLMASK 0xffffffffu

static __device__ float g_hm2[32768];

constexpr int NQ  = 8192;
constexpr int NC  = 32768;
constexpr int DK  = 64;
constexpr int QT  = 64;       // queries per CTA
constexpr int RQ  = 8;        // queries per warp
constexpr int CT  = 256;      // centers per chunk
constexpr int NCHUNK = NC / CT;   // 128
constexpr int MUS = 68;       // smem row stride (floats)

constexpr int RV_OFF = 0;
constexpr int RE_OFF = NQ * 128;
constexpr int G_OFF  = RE_OFF + NQ * 4;

// smem layout (floats)
constexpr int OFF_Q   = 0;                        // 64*68 = 4352
constexpr int OFF_MU  = OFF_Q + QT * MUS;         // 2*256*68 = 34816
constexpr int OFF_HM2 = OFF_MU + 2 * CT * MUS;    // 2*256 = 512
constexpr int OFF_CU  = OFF_HM2 + 2 * CT;         // 64 q * 32 = 2048
constexpr int OFF_CI  = OFF_CU + QT * 32;         // 2048
constexpr int OFF_SCR = OFF_CI + QT * 32;         // 8*64 = 512
constexpr int SMEM_FLOATS = OFF_SCR + 8 * 64;     // 44288 floats = 177152 B

__global__ void hm2_kernel(const float* __restrict__ mu) {
    int c = blockIdx.x * 256 + threadIdx.x;
    const float4* r = reinterpret_cast<const float4*>(mu) + (size_t)c * 16;
    float s = 0.f;
#pragma unroll
    for (int j = 0; j < 16; j++) {
        float4 v = r[j];
        s += v.x * v.x + v.y * v.y + v.z * v.z + v.w * v.w;
    }
    g_hm2[c] = 0.5f * s;
}

// order-preserving float <-> uint
__device__ __forceinline__ unsigned fenc(float f) {
    unsigned u = __float_as_uint(f);
    return (u & 0x80000000u) ? ~u : (u | 0x80000000u);
}
__device__ __forceinline__ float fdec(unsigned u) {
    return (u & 0x80000000u) ? __uint_as_float(u & 0x7fffffffu)
                             : __uint_as_float(~u);
}
__device__ __forceinline__ unsigned redux_min_u32(unsigned v) {
    unsigned r;
    asm("redux.sync.min.u32 %0, %1, 0xffffffff;" : "=r"(r) : "r"(v));
    return r;
}

__global__ __launch_bounds__(256, 1)
void ma_kernel(const float* __restrict__ x,
               const float* __restrict__ q_tilde,
               const float* __restrict__ g_prior,
               const float* __restrict__ mu,
               const float* __restrict__ V,
               const float* __restrict__ E,
               const float* __restrict__ sig,
               const float* __restrict__ Wg,
               const float* __restrict__ Wgb,
               const float* __restrict__ gpw,
               float* __restrict__ out) {
    extern __shared__ float sm[];
    float*    sQ   = sm + OFF_Q;
    float*    sMu  = sm + OFF_MU;
    float*    sHm2 = sm + OFF_HM2;
    unsigned* sCu  = reinterpret_cast<unsigned*>(sm + OFF_CU);
    int*      sCi  = reinterpret_cast<int*>(sm + OFF_CI);
    float*    sScr = sm + OFF_SCR;

    const int tid  = threadIdx.x;
    const int lane = tid & 31;
    const int wid  = tid >> 5;
    const int q0   = blockIdx.x * QT;

    // ---- stage Q tile: sQ[q][k], 64 q x 64 k ----
#pragma unroll
    for (int j = 0; j < 16; j++) {
        int idx = tid + 256 * j;
        int q = idx >> 6, k = idx & 63;
        sQ[q * MUS + k] = q_tilde[(size_t)(q0 + q) * DK + k];
    }

    // ---- init top-k candidate arrays (all -inf) ----
    const unsigned NEGINF_U = fenc(-INFINITY);
#pragma unroll
    for (int j = 0; j < 8; j++) {
        sCu[tid + 256 * j] = NEGINF_U;
        sCi[tid + 256 * j] = 0;
    }

    const uint32_t smuA = (uint32_t)__cvta_generic_to_shared(sMu);
    const uint32_t shmA = (uint32_t)__cvta_generic_to_shared(sHm2);

    auto issue_chunk = [&](int chunk) {
        int buf = chunk & 1;
        uint32_t mdst = smuA + (uint32_t)(buf * (CT * MUS * 4));
        const float* src = mu + (size_t)chunk * CT * DK;
#pragma unroll
        for (int j = 0; j < 16; j++) {
            int idx = tid + 256 * j;            // 256 rows x 16 float4
            int c = idx >> 4, kq = idx & 15;
            asm volatile("cp.async.cg.shared.global [%0], [%1], 16;\n"
                         :: "r"(mdst + (uint32_t)((c * MUS + kq * 4) * 4)),
                            "l"(src + c * DK + kq * 4));
        }
        if (tid < 64) {
            asm volatile("cp.async.cg.shared.global [%0], [%1], 16;\n"
                         :: "r"(shmA + (uint32_t)(buf * CT * 4 + tid * 16)),
                            "l"(g_hm2 + chunk * CT + tid * 4));
        }
        asm volatile("cp.async.commit_group;\n");
    };

    issue_chunk(0);

    // per-query running 32nd-best threshold (warp wid owns q = 8*wid + r)
    float thr[RQ];
#pragma unroll
    for (int r = 0; r < RQ; r++) thr[r] = -INFINITY;

    const float* qb = sQ + (RQ * wid) * MUS;
    unsigned* myCu = sCu + (RQ * wid) * 32;   // [r][lane]
    int*      myCi = sCi + (RQ * wid) * 32;

    for (int ch = 0; ch < NCHUNK; ++ch) {
        asm volatile("cp.async.wait_group 0;\n");
        __syncthreads();                       // buffer + hm2 visible
        if (ch + 1 < NCHUNK) issue_chunk(ch + 1);

        const float* mb = sMu + (ch & 1) * (CT * MUS);
        const float* hb = sHm2 + (ch & 1) * CT;

        // ---- GEMM: 8q x 8c per thread, packed f32x2 FMA ----
        unsigned long long acc[RQ][8];
#pragma unroll
        for (int r = 0; r < RQ; r++)
#pragma unroll
            for (int s = 0; s < 8; s++) acc[r][s] = 0ull;

        const float* mrow = mb + lane * MUS;
#pragma unroll 4
        for (int k = 0; k < DK; k += 4) {
            ulonglong2 qv[RQ];
#pragma unroll
            for (int r = 0; r < RQ; r++)
                qv[r] = *reinterpret_cast<const ulonglong2*>(qb + r * MUS + k);
#pragma unroll
            for (int s = 0; s < 8; s++) {
                ulonglong2 cv = *reinterpret_cast<const ulonglong2*>(
                    mrow + (32 * s) * MUS + k);
#pragma unroll
                for (int r = 0; r < RQ; r++) {
                    asm("fma.rn.f32x2 %0, %1, %2, %0;"
                        : "+l"(acc[r][s]) : "l"(qv[r].x), "l"(cv.x));
                    asm("fma.rn.f32x2 %0, %1, %2, %0;"
                        : "+l"(acc[r][s]) : "l"(qv[r].y), "l"(cv.y));
                }
            }
        }

        // scores s' = q.mu - 0.5||mu||^2
        float h[8];
#pragma unroll
        for (int s = 0; s < 8; s++) h[s] = hb[lane + 32 * s];

        const int base = ch * CT;
#pragma unroll
        for (int r = 0; r < RQ; r++) {
            float sc[8];
#pragma unroll
            for (int s = 0; s < 8; s++) {
                float2 f = *reinterpret_cast<float2*>(&acc[r][s]);
                sc[s] = f.x + f.y - h[s];
            }
            float vm = sc[0];
#pragma unroll
            for (int s = 1; s < 8; s++) vm = fmaxf(vm, sc[s]);

            if (__ballot_sync(FULLMASK, vm > thr[r])) {
#pragma unroll
                for (int s = 0; s < 8; s++) {
                    float v = sc[s];
                    unsigned m = __ballot_sync(FULLMASK, v > thr[r]);
                    int segbase = base + 32 * s;
                    while (m) {
                        int src = __ffs(m) - 1;
                        m &= m - 1;
                        float nv = __shfl_sync(FULLMASK, v, src);
                        if (nv > thr[r]) {
                            unsigned my = myCu[r * 32 + lane];
                            unsigned thrU = fenc(thr[r]);
                            unsigned bl = __ballot_sync(FULLMASK, my == thrU);
                            int ml = __ffs(bl) - 1;
                            if (lane == ml) {
                                my = fenc(nv);
                                myCu[r * 32 + lane] = my;
                                myCi[r * 32 + lane] = segbase + src;
                            }
                            thr[r] = fdec(redux_min_u32(my));
                        }
                    }
                }
            }
        }
    }

    __syncthreads();

    const float sigma  = sig[0];
    const float inv_s2 = 1.f / (sigma * sigma);
    const float bgate  = Wgb[0];
    const float gw     = gpw[0];

    float* myW = sScr + wid * 64;
    int*   myI = reinterpret_cast<int*>(myW + 32);

    // ---- epilogue: 8 rounds; warp w handles q = w + 8*round ----
#pragma unroll
    for (int round = 0; round < 8; ++round) {
        int q  = wid + 8 * round;      // owner warp = round, sub-index = wid
        int qg = q0 + q;

        float sv  = fdec(sCu[(round * 8 + wid) * 32 + lane]);
        int   idx = sCi[(round * 8 + wid) * 32 + lane];
        float s = sv * inv_s2;
        float mx = s;
#pragma unroll
        for (int off = 16; off; off >>= 1)
            mx = fmaxf(mx, __shfl_xor_sync(FULLMASK, mx, off));
        float e = __expf(s - mx);
        float se = e;
#pragma unroll
        for (int off = 16; off; off >>= 1)
            se += __shfl_xor_sync(FULLMASK, se, off);
        float wgt = e / se;

        myW[lane] = wgt;
        myI[lane] = idx;
        __syncwarp();

        // r_V: lane owns dims [4*lane, 4*lane+4)
        float4 acc = make_float4(0.f, 0.f, 0.f, 0.f);
#pragma unroll 4
        for (int k = 0; k < 32; k++) {
            float wk = myW[k];
            size_t row = (size_t)myI[k];
            float4 v = reinterpret_cast<const float4*>(V + row * 128)[lane];
            acc.x += wk * v.x; acc.y += wk * v.y;
            acc.z += wk * v.z; acc.w += wk * v.w;
        }

        // r_E (4 dims)
        float re = 0.f;
        if (lane < 4) {
            for (int k = 0; k < 32; k++)
                re += myW[k] * E[(size_t)myI[k] * 4 + lane];
        }

        // gate
        const float4 wv = reinterpret_cast<const float4*>(Wg + 256)[lane];
        float tot = acc.x * wv.x + acc.y * wv.y + acc.z * wv.z + acc.w * wv.w;
        const float* xq = x + (size_t)qg * 256;
#pragma unroll
        for (int u = 0; u < 8; u++) {
            int t = lane + 32 * u;
            tot += xq[t] * Wg[t];
        }
#pragma unroll
        for (int off = 16; off; off >>= 1)
            tot += __shfl_xor_sync(FULLMASK, tot, off);

        reinterpret_cast<float4*>(out + RV_OFF + (size_t)qg * 128)[lane] = acc;
        if (lane < 4) out[RE_OFF + (size_t)qg * 4 + lane] = re;
        if (lane == 0) {
            float z = tot + bgate + gw * g_prior[qg];
            out[G_OFF + qg] = 1.f / (1.f + __expf(-z));
        }
        __syncwarp();
    }
}

extern "C" void kernel_launch(void* const* d_in, const int* in_sizes, int n_in,
                              void* d_out, int out_size) {
    (void)in_sizes; (void)n_in; (void)out_size;
    const float* x   = (const float*)d_in[0];
    const float* qt  = (const float*)d_in[1];
    const float* gp  = (const float*)d_in[2];
    const float* mu  = (const float*)d_in[3];
    const float* V   = (const float*)d_in[4];
    const float* E   = (const float*)d_in[5];
    const float* sg  = (const float*)d_in[6];
    const float* Wg  = (const float*)d_in[7];
    const float* Wb  = (const float*)d_in[8];
    const float* gw  = (const float*)d_in[9];

    hm2_kernel<<<NC / 256, 256>>>(mu);

    const int smem_bytes = SMEM_FLOATS * 4;
    cudaFuncSetAttribute(ma_kernel, cudaFuncAttributeMaxDynamicSharedMemorySize,
                         smem_bytes);
    ma_kernel<<<NQ / QT, 256, smem_bytes>>>(x, qt, gp, mu, V, E, sg, Wg, Wb, gw,
                                            (float*)d_out);
}

// round 5
// speedup vs baseline: 1.0366x; 1.0366x over previous
#include <cuda_runtime.h>
#include <cstdint>

// ---------------------------------------------------------------------------
// MemoryAttention R5: R4 (mixed 2-D warp tiling, 4q x 4c threads, 2 CTA/SM)
// + fix: __syncthreads() before reusing sS as the top-k publish buffer
// (cross-warp race between last-chunk selection reads and publish writes).
// ---------------------------------------------------------------------------

#define FULLMASK 0xffffffffu

static __device__ float g_hm2[32768];

constexpr int NQ  = 8192;
constexpr int NC  = 32768;
constexpr int DK  = 64;
constexpr int QT  = 32;       // queries per CTA
constexpr int CT  = 128;      // centers per chunk
constexpr int NCHUNK = NC / CT;   // 256
constexpr int MUS  = 68;      // smem row stride (floats)
constexpr int SSTR = 132;     // score row stride

constexpr int RV_OFF = 0;
constexpr int RE_OFF = NQ * 128;
constexpr int G_OFF  = RE_OFF + NQ * 4;

// smem layout (floats)
constexpr int OFF_Q   = 0;                        // 32*68  = 2176
constexpr int OFF_MU  = OFF_Q + QT * MUS;         // 2*128*68 = 17408
constexpr int OFF_HM2 = OFF_MU + 2 * CT * MUS;    // 256
constexpr int OFF_S   = OFF_HM2 + 2 * CT;         // 32*132 = 4224
constexpr int OFF_SCR = OFF_S + QT * SSTR;        // 512
constexpr int SMEM_FLOATS = OFF_SCR + 8 * 64;     // 24576 floats = 98304 B

__global__ void hm2_kernel(const float* __restrict__ mu) {
    int c = blockIdx.x * 256 + threadIdx.x;
    const float4* r = reinterpret_cast<const float4*>(mu) + (size_t)c * 16;
    float s = 0.f;
#pragma unroll
    for (int j = 0; j < 16; j++) {
        float4 v = r[j];
        s += v.x * v.x + v.y * v.y + v.z * v.z + v.w * v.w;
    }
    g_hm2[c] = 0.5f * s;
}

// order-preserving float <-> uint
__device__ __forceinline__ unsigned fenc(float f) {
    unsigned u = __float_as_uint(f);
    return (u & 0x80000000u) ? ~u : (u | 0x80000000u);
}
__device__ __forceinline__ float fdec(unsigned u) {
    return (u & 0x80000000u) ? __uint_as_float(u & 0x7fffffffu)
                             : __uint_as_float(~u);
}
__device__ __forceinline__ unsigned redux_min_u32(unsigned v) {
    unsigned r;
    asm("redux.sync.min.u32 %0, %1, 0xffffffff;" : "=r"(r) : "r"(v));
    return r;
}

__global__ __launch_bounds__(256, 2)
void ma_kernel(const float* __restrict__ x,
               const float* __restrict__ q_tilde,
               const float* __restrict__ g_prior,
               const float* __restrict__ mu,
               const float* __restrict__ V,
               const float* __restrict__ E,
               const float* __restrict__ sig,
               const float* __restrict__ Wg,
               const float* __restrict__ Wgb,
               const float* __restrict__ gpw,
               float* __restrict__ out) {
    extern __shared__ float sm[];
    float* sQ   = sm + OFF_Q;
    float* sMu  = sm + OFF_MU;
    float* sHm2 = sm + OFF_HM2;
    float* sS   = sm + OFF_S;
    float* sScr = sm + OFF_SCR;

    const int tid  = threadIdx.x;
    const int lane = tid & 31;
    const int wid  = tid >> 5;
    const int q0   = blockIdx.x * QT;

    // 2-D warp grid: wq in {0,1}, wc in {0..3}; lane grid: qg 0..3, cg 0..7
    const int wq = wid >> 2;
    const int wc = wid & 3;
    const int qg = lane >> 3;
    const int cg = lane & 7;

    // ---- stage Q tile: sQ[q][k], 32 q x 64 k ----
#pragma unroll
    for (int j = 0; j < 8; j++) {
        int idx = tid + 256 * j;
        int q = idx >> 6, k = idx & 63;
        sQ[q * MUS + k] = q_tilde[(size_t)(q0 + q) * DK + k];
    }

    const uint32_t smuA = (uint32_t)__cvta_generic_to_shared(sMu);
    const uint32_t shmA = (uint32_t)__cvta_generic_to_shared(sHm2);

    auto issue_chunk = [&](int chunk) {
        int buf = chunk & 1;
        uint32_t mdst = smuA + (uint32_t)(buf * (CT * MUS * 4));
        const float* src = mu + (size_t)chunk * CT * DK;
#pragma unroll
        for (int j = 0; j < 8; j++) {
            int idx = tid + 256 * j;            // 128 rows x 16 float4
            int c = idx >> 4, kq = idx & 15;
            asm volatile("cp.async.cg.shared.global [%0], [%1], 16;\n"
                         :: "r"(mdst + (uint32_t)((c * MUS + kq * 4) * 4)),
                            "l"(src + c * DK + kq * 4));
        }
        if (tid < 32) {
            asm volatile("cp.async.cg.shared.global [%0], [%1], 16;\n"
                         :: "r"(shmA + (uint32_t)(buf * CT * 4 + tid * 16)),
                            "l"(g_hm2 + chunk * CT + tid * 4));
        }
        asm volatile("cp.async.commit_group;\n");
    };

    issue_chunk(0);

    // selection state: warp wid owns queries 4*wid + r (register-resident)
    unsigned cu[4]; int ci[4]; float thr[4];
    const unsigned NEGINF_U = fenc(-INFINITY);
#pragma unroll
    for (int r = 0; r < 4; r++) { cu[r] = NEGINF_U; ci[r] = 0; thr[r] = -INFINITY; }

    const float* qbase = sQ + (16 * wq + qg) * MUS;   // + 4r*MUS
    float* sSrow = sS + (16 * wq + qg) * SSTR + 32 * wc + cg;

    for (int ch = 0; ch < NCHUNK; ++ch) {
        asm volatile("cp.async.wait_group 0;\n");
        __syncthreads();                        // mu buf + prev select done
        if (ch + 1 < NCHUNK) issue_chunk(ch + 1);

        const float* mb = sMu + (ch & 1) * (CT * MUS);
        const float* hb = sHm2 + (ch & 1) * CT;
        const float* cbase = mb + (32 * wc + cg) * MUS;   // + 8s*MUS

        // ---- GEMM: 4q x 4c per thread, packed f32x2 FMA ----
        unsigned long long acc[4][4];
#pragma unroll
        for (int r = 0; r < 4; r++)
#pragma unroll
            for (int s = 0; s < 4; s++) acc[r][s] = 0ull;

#pragma unroll
        for (int k = 0; k < DK; k += 4) {
            ulonglong2 qv[4];
#pragma unroll
            for (int r = 0; r < 4; r++)
                qv[r] = *reinterpret_cast<const ulonglong2*>(qbase + (4 * r) * MUS + k);
#pragma unroll
            for (int s = 0; s < 4; s++) {
                ulonglong2 cv = *reinterpret_cast<const ulonglong2*>(
                    cbase + (8 * s) * MUS + k);
#pragma unroll
                for (int r = 0; r < 4; r++) {
                    asm("fma.rn.f32x2 %0, %1, %2, %0;"
                        : "+l"(acc[r][s]) : "l"(qv[r].x), "l"(cv.x));
                    asm("fma.rn.f32x2 %0, %1, %2, %0;"
                        : "+l"(acc[r][s]) : "l"(qv[r].y), "l"(cv.y));
                }
            }
        }

        // scores s' = q.mu - 0.5||mu||^2 -> transpose via sS
#pragma unroll
        for (int r = 0; r < 4; r++)
#pragma unroll
            for (int s = 0; s < 4; s++) {
                float2 f = *reinterpret_cast<float2*>(&acc[r][s]);
                float sc = f.x + f.y - hb[32 * wc + cg + 8 * s];
                sSrow[(4 * r) * SSTR + 8 * s] = sc;
            }
        __syncthreads();

        // ---- streaming top-32: warp wid owns q = 4*wid + r ----
        const int base = ch * CT;
#pragma unroll
        for (int r = 0; r < 4; r++) {
            const float* row = sS + (4 * wid + r) * SSTR;
            float sc4[4];
#pragma unroll
            for (int s = 0; s < 4; s++) sc4[s] = row[lane + 32 * s];
            float vm = fmaxf(fmaxf(sc4[0], sc4[1]), fmaxf(sc4[2], sc4[3]));
            if (__ballot_sync(FULLMASK, vm > thr[r])) {
#pragma unroll
                for (int s = 0; s < 4; s++) {
                    float v = sc4[s];
                    unsigned m = __ballot_sync(FULLMASK, v > thr[r]);
                    int segbase = base + 32 * s;
                    while (m) {
                        int src = __ffs(m) - 1;
                        m &= m - 1;
                        float nv = __shfl_sync(FULLMASK, v, src);
                        if (nv > thr[r]) {
                            unsigned thrU = fenc(thr[r]);
                            unsigned bl = __ballot_sync(FULLMASK, cu[r] == thrU);
                            int ml = __ffs(bl) - 1;
                            if (lane == ml) { cu[r] = fenc(nv); ci[r] = segbase + src; }
                            thr[r] = fdec(redux_min_u32(cu[r]));
                        }
                    }
                }
            }
        }
        // next top-of-loop barrier orders select reads before sS overwrite
    }

    // FIX (R5): order all warps' final selection reads of sS before reusing
    // sS as the publish buffer below. Without this, warp w's publish to
    // sS[128w..] races another warp's last-chunk selection reads (stride-132
    // rows overlap the publish region) -> corrupted top-k (R4: rel_err 0.26).
    __syncthreads();

    // ---- publish top-32 per query (reuse sS) ----
    float* sTopV = sS;                       // [q][lane]
    int*   sTopI = reinterpret_cast<int*>(sS + QT * 32);
#pragma unroll
    for (int r = 0; r < 4; r++) {
        int q = 4 * wid + r;
        sTopV[q * 32 + lane] = fdec(cu[r]);
        sTopI[q * 32 + lane] = ci[r];
    }
    __syncthreads();

    const float sigma  = sig[0];
    const float inv_s2 = 1.f / (sigma * sigma);
    const float bgate  = Wgb[0];
    const float gw     = gpw[0];

    float* myW = sScr + wid * 64;
    int*   myI = reinterpret_cast<int*>(myW + 32);

    // ---- epilogue: softmax + gathers + gate; warp w handles q = w + 8*round
#pragma unroll
    for (int round = 0; round < 4; ++round) {
        int q  = wid + 8 * round;
        int qg2 = q0 + q;

        float sv  = sTopV[q * 32 + lane];
        int   idx = sTopI[q * 32 + lane];
        float s = sv * inv_s2;
        float mx = s;
#pragma unroll
        for (int off = 16; off; off >>= 1)
            mx = fmaxf(mx, __shfl_xor_sync(FULLMASK, mx, off));
        float e = __expf(s - mx);
        float se = e;
#pragma unroll
        for (int off = 16; off; off >>= 1)
            se += __shfl_xor_sync(FULLMASK, se, off);
        float wgt = e / se;

        myW[lane] = wgt;
        myI[lane] = idx;
        __syncwarp();

        // r_V: lane owns dims [4*lane, 4*lane+4)
        float4 acc = make_float4(0.f, 0.f, 0.f, 0.f);
#pragma unroll 4
        for (int k = 0; k < 32; k++) {
            float wk = myW[k];
            size_t row = (size_t)myI[k];
            float4 v = reinterpret_cast<const float4*>(V + row * 128)[lane];
            acc.x += wk * v.x; acc.y += wk * v.y;
            acc.z += wk * v.z; acc.w += wk * v.w;
        }

        // r_E (4 dims)
        float re = 0.f;
        if (lane < 4) {
            for (int k = 0; k < 32; k++)
                re += myW[k] * E[(size_t)myI[k] * 4 + lane];
        }

        // gate: sigmoid( x.W1 + rV.W2 + b + gpw * g_prior )
        const float4 wv = reinterpret_cast<const float4*>(Wg + 256)[lane];
        float tot = acc.x * wv.x + acc.y * wv.y + acc.z * wv.z + acc.w * wv.w;
        const float* xq = x + (size_t)qg2 * 256;
#pragma unroll
        for (int u = 0; u < 8; u++) {
            int t = lane + 32 * u;
            tot += xq[t] * Wg[t];
        }
#pragma unroll
        for (int off = 16; off; off >>= 1)
            tot += __shfl_xor_sync(FULLMASK, tot, off);

        reinterpret_cast<float4*>(out + RV_OFF + (size_t)qg2 * 128)[lane] = acc;
        if (lane < 4) out[RE_OFF + (size_t)qg2 * 4 + lane] = re;
        if (lane == 0) {
            float z = tot + bgate + gw * g_prior[qg2];
            out[G_OFF + qg2] = 1.f / (1.f + __expf(-z));
        }
        __syncwarp();
    }
}

extern "C" void kernel_launch(void* const* d_in, const int* in_sizes, int n_in,
                              void* d_out, int out_size) {
    (void)in_sizes; (void)n_in; (void)out_size;
    const float* x   = (const float*)d_in[0];
    const float* qt  = (const float*)d_in[1];
    const float* gp  = (const float*)d_in[2];
    const float* mu  = (const float*)d_in[3];
    const float* V   = (const float*)d_in[4];
    const float* E   = (const float*)d_in[5];
    const float* sg  = (const float*)d_in[6];
    const float* Wg  = (const float*)d_in[7];
    const float* Wb  = (const float*)d_in[8];
    const float* gw  = (const float*)d_in[9];

    hm2_kernel<<<NC / 256, 256>>>(mu);

    const int smem_bytes = SMEM_FLOATS * 4;   // 98304
    cudaFuncSetAttribute(ma_kernel, cudaFuncAttributeMaxDynamicSharedMemorySize,
                         smem_bytes);
    ma_kernel<<<NQ / QT, 256, smem_bytes>>>(x, qt, gp, mu, V, E, sg, Wg, Wb, gw,
                                            (float*)d_out);
}

// round 6
// speedup vs baseline: 1.8448x; 1.7796x over previous
#include <cuda_runtime.h>
#include <cstdint>

// ---------------------------------------------------------------------------
// MemoryAttention R6: score GEMM on tensor cores (mma.sync m16n8k8 tf32).
//   - mu pre-converted to tf32 (rna) in prologue; exact hm2 kept in fp32.
//   - Q converted to tf32 A-fragments ONCE (registers, reused all 256 chunks).
//   - selection on tf32 scores (ballot/redux streaming top-32, proven R2/R5);
//   - epilogue rescores the selected 32 indices EXACTLY in fp32, so softmax
//     weights / outputs are exact; tf32 only influences set membership at
//     near-ties (output-invariant).
// ---------------------------------------------------------------------------

#define FULLMASK 0xffffffffu

static __device__ float g_hm2[32768];
static __device__ float g_mu_tf32[32768 * 64];   // tf32-rounded mu (8 MB)

constexpr int NQ  = 8192;
constexpr int NC  = 32768;
constexpr int DK  = 64;
constexpr int QT  = 32;       // queries per CTA
constexpr int CT  = 128;      // centers per chunk
constexpr int NCHUNK = NC / CT;   // 256
constexpr int MUS  = 68;      // smem row stride (floats)
constexpr int SSTR = 132;     // score row stride

constexpr int RV_OFF = 0;
constexpr int RE_OFF = NQ * 128;
constexpr int G_OFF  = RE_OFF + NQ * 4;

// smem layout (floats)
constexpr int OFF_Q   = 0;                        // 32*68  = 2176
constexpr int OFF_MU  = OFF_Q + QT * MUS;         // 2*128*68 = 17408
constexpr int OFF_HM2 = OFF_MU + 2 * CT * MUS;    // 256
constexpr int OFF_S   = OFF_HM2 + 2 * CT;         // 32*132 = 4224
constexpr int OFF_SCR = OFF_S + QT * SSTR;        // 512
constexpr int SMEM_FLOATS = OFF_SCR + 8 * 64;     // 24576 floats = 98304 B

__device__ __forceinline__ uint32_t to_tf32(float f) {
    uint32_t u;
    asm("cvt.rna.tf32.f32 %0, %1;" : "=r"(u) : "f"(f));
    return u;
}

__global__ void prep_kernel(const float* __restrict__ mu) {
    int c = blockIdx.x * 256 + threadIdx.x;   // 128 x 256 = 32768 rows
    const float4* r = reinterpret_cast<const float4*>(mu) + (size_t)c * 16;
    float4* w = reinterpret_cast<float4*>(g_mu_tf32) + (size_t)c * 16;
    float s = 0.f;
#pragma unroll
    for (int j = 0; j < 16; j++) {
        float4 v = r[j];
        s += v.x * v.x + v.y * v.y + v.z * v.z + v.w * v.w;
        float4 t;
        t.x = __uint_as_float(to_tf32(v.x));
        t.y = __uint_as_float(to_tf32(v.y));
        t.z = __uint_as_float(to_tf32(v.z));
        t.w = __uint_as_float(to_tf32(v.w));
        w[j] = t;
    }
    g_hm2[c] = 0.5f * s;
}

// order-preserving float <-> uint
__device__ __forceinline__ unsigned fenc(float f) {
    unsigned u = __float_as_uint(f);
    return (u & 0x80000000u) ? ~u : (u | 0x80000000u);
}
__device__ __forceinline__ float fdec(unsigned u) {
    return (u & 0x80000000u) ? __uint_as_float(u & 0x7fffffffu)
                             : __uint_as_float(~u);
}
__device__ __forceinline__ unsigned redux_min_u32(unsigned v) {
    unsigned r;
    asm("redux.sync.min.u32 %0, %1, 0xffffffff;" : "=r"(r) : "r"(v));
    return r;
}

__device__ __forceinline__ void mma_tf32(float* d, const uint32_t* a,
                                         uint32_t b0, uint32_t b1) {
    asm("mma.sync.aligned.m16n8k8.row.col.f32.tf32.tf32.f32 "
        "{%0,%1,%2,%3}, {%4,%5,%6,%7}, {%8,%9}, {%0,%1,%2,%3};"
        : "+f"(d[0]), "+f"(d[1]), "+f"(d[2]), "+f"(d[3])
        : "r"(a[0]), "r"(a[1]), "r"(a[2]), "r"(a[3]), "r"(b0), "r"(b1));
}

__global__ __launch_bounds__(256, 2)
void ma_kernel(const float* __restrict__ x,
               const float* __restrict__ q_tilde,
               const float* __restrict__ g_prior,
               const float* __restrict__ mu,
               const float* __restrict__ V,
               const float* __restrict__ E,
               const float* __restrict__ sig,
               const float* __restrict__ Wg,
               const float* __restrict__ Wgb,
               const float* __restrict__ gpw,
               float* __restrict__ out) {
    extern __shared__ float sm[];
    float* sQ   = sm + OFF_Q;
    float* sMu  = sm + OFF_MU;
    float* sHm2 = sm + OFF_HM2;
    float* sS   = sm + OFF_S;
    float* sScr = sm + OFF_SCR;

    const int tid  = threadIdx.x;
    const int lane = tid & 31;
    const int wid  = tid >> 5;
    const int q0   = blockIdx.x * QT;

    // warp grid: wq in {0,1} (16 q-rows each), wc in {0..3} (32 centers each)
    const int wq = wid >> 2;
    const int wc = wid & 3;
    const int tr = lane >> 2;   // 0..7
    const int tc = lane & 3;    // 0..3

    // ---- stage Q tile: sQ[q][k], 32 q x 64 k ----
#pragma unroll
    for (int j = 0; j < 8; j++) {
        int idx = tid + 256 * j;
        int q = idx >> 6, k = idx & 63;
        sQ[q * MUS + k] = q_tilde[(size_t)(q0 + q) * DK + k];
    }

    const uint32_t smuA = (uint32_t)__cvta_generic_to_shared(sMu);
    const uint32_t shmA = (uint32_t)__cvta_generic_to_shared(sHm2);

    auto issue_chunk = [&](int chunk) {
        int buf = chunk & 1;
        uint32_t mdst = smuA + (uint32_t)(buf * (CT * MUS * 4));
        const float* src = g_mu_tf32 + (size_t)chunk * CT * DK;
#pragma unroll
        for (int j = 0; j < 8; j++) {
            int idx = tid + 256 * j;            // 128 rows x 16 float4
            int c = idx >> 4, kq = idx & 15;
            asm volatile("cp.async.cg.shared.global [%0], [%1], 16;\n"
                         :: "r"(mdst + (uint32_t)((c * MUS + kq * 4) * 4)),
                            "l"(src + c * DK + kq * 4));
        }
        if (tid < 32) {
            asm volatile("cp.async.cg.shared.global [%0], [%1], 16;\n"
                         :: "r"(shmA + (uint32_t)(buf * CT * 4 + tid * 16)),
                            "l"(g_hm2 + chunk * CT + tid * 4));
        }
        asm volatile("cp.async.commit_group;\n");
    };

    issue_chunk(0);
    __syncthreads();   // sQ visible to all (A-fragment loads below)

    // ---- A fragments: Q tile 16x64 per wq, tf32, loaded ONCE ----
    uint32_t af[8][4];
    {
        const float* qa = sQ + (16 * wq + tr) * MUS + tc;
#pragma unroll
        for (int kt = 0; kt < 8; kt++) {
            af[kt][0] = to_tf32(qa[8 * kt]);
            af[kt][1] = to_tf32(qa[8 * MUS + 8 * kt]);
            af[kt][2] = to_tf32(qa[8 * kt + 4]);
            af[kt][3] = to_tf32(qa[8 * MUS + 8 * kt + 4]);
        }
    }

    // selection state: warp wid owns queries 4*wid + r
    unsigned cu[4]; int ci[4]; float thr[4];
    const unsigned NEGINF_U = fenc(-INFINITY);
#pragma unroll
    for (int r = 0; r < 4; r++) { cu[r] = NEGINF_U; ci[r] = 0; thr[r] = -INFINITY; }

    for (int ch = 0; ch < NCHUNK; ++ch) {
        asm volatile("cp.async.wait_group 0;\n");
        __syncthreads();                        // mu buf ready; prev select done
        if (ch + 1 < NCHUNK) issue_chunk(ch + 1);

        const float* mb = sMu + (ch & 1) * (CT * MUS);
        const float* hb = sHm2 + (ch & 1) * CT;

        // ---- tensor-core GEMM: warp tile 16q x 32c, 8 k-tiles x 4 n-tiles ----
        float acc[4][4];
#pragma unroll
        for (int nt = 0; nt < 4; nt++)
#pragma unroll
            for (int j = 0; j < 4; j++) acc[nt][j] = 0.f;

        const float* bp = mb + (32 * wc + tr) * MUS + tc;
#pragma unroll
        for (int kt = 0; kt < 8; kt++) {
#pragma unroll
            for (int nt = 0; nt < 4; nt++) {
                uint32_t b0 = __float_as_uint(bp[(8 * nt) * MUS + 8 * kt]);
                uint32_t b1 = __float_as_uint(bp[(8 * nt) * MUS + 8 * kt + 4]);
                mma_tf32(acc[nt], af[kt], b0, b1);
            }
        }

        // scores s' = q.mu - 0.5||mu||^2 -> sS[q][c] (float2 stores)
        {
            const float* hbase = hb + 32 * wc + 2 * tc;
            float* srow = sS + (16 * wq + tr) * SSTR + 32 * wc + 2 * tc;
#pragma unroll
            for (int nt = 0; nt < 4; nt++) {
                float2 h = *reinterpret_cast<const float2*>(hbase + 8 * nt);
                float2 lo, hi;
                lo.x = acc[nt][0] - h.x;  lo.y = acc[nt][1] - h.y;
                hi.x = acc[nt][2] - h.x;  hi.y = acc[nt][3] - h.y;
                *reinterpret_cast<float2*>(srow + 8 * nt) = lo;
                *reinterpret_cast<float2*>(srow + 8 * SSTR + 8 * nt) = hi;
            }
        }
        __syncthreads();

        // ---- streaming top-32: warp wid owns q = 4*wid + r ----
        const int base = ch * CT;
#pragma unroll
        for (int r = 0; r < 4; r++) {
            const float* row = sS + (4 * wid + r) * SSTR;
            float sc4[4];
#pragma unroll
            for (int s = 0; s < 4; s++) sc4[s] = row[lane + 32 * s];
            float vm = fmaxf(fmaxf(sc4[0], sc4[1]), fmaxf(sc4[2], sc4[3]));
            if (__ballot_sync(FULLMASK, vm > thr[r])) {
#pragma unroll
                for (int s = 0; s < 4; s++) {
                    float v = sc4[s];
                    unsigned m = __ballot_sync(FULLMASK, v > thr[r]);
                    int segbase = base + 32 * s;
                    while (m) {
                        int src = __ffs(m) - 1;
                        m &= m - 1;
                        float nv = __shfl_sync(FULLMASK, v, src);
                        if (nv > thr[r]) {
                            unsigned thrU = fenc(thr[r]);
                            unsigned bl = __ballot_sync(FULLMASK, cu[r] == thrU);
                            int ml = __ffs(bl) - 1;
                            if (lane == ml) { cu[r] = fenc(nv); ci[r] = segbase + src; }
                            thr[r] = fdec(redux_min_u32(cu[r]));
                        }
                    }
                }
            }
        }
        // next top-of-loop barrier orders select reads before sS overwrite
    }

    // order all final selection reads before reusing sS as publish buffer
    __syncthreads();

    // ---- publish top-32 indices per query (reuse sS) ----
    int* sTopI = reinterpret_cast<int*>(sS);
#pragma unroll
    for (int r = 0; r < 4; r++) {
        int q = 4 * wid + r;
        sTopI[q * 32 + lane] = ci[r];
    }
    __syncthreads();

    const float sigma  = sig[0];
    const float inv_s2 = 1.f / (sigma * sigma);
    const float bgate  = Wgb[0];
    const float gw     = gpw[0];

    float* myW = sScr + wid * 64;
    int*   myI = reinterpret_cast<int*>(myW + 32);

    // ---- epilogue: EXACT rescore + softmax + gathers + gate ----
#pragma unroll
    for (int round = 0; round < 4; ++round) {
        int q   = wid + 8 * round;
        int qg2 = q0 + q;

        int idx = sTopI[q * 32 + lane];

        // exact fp32 score: q . mu[idx] - 0.5||mu[idx]||^2
        const float4* mrow = reinterpret_cast<const float4*>(mu + (size_t)idx * DK);
        const float4* qrow = reinterpret_cast<const float4*>(sQ + q * MUS);
        float d0 = 0.f, d1 = 0.f, d2 = 0.f, d3 = 0.f;
#pragma unroll
        for (int j = 0; j < 16; j += 4) {
            float4 m0 = mrow[j],     qv0 = qrow[j];
            float4 m1 = mrow[j + 1], qv1 = qrow[j + 1];
            float4 m2 = mrow[j + 2], qv2 = qrow[j + 2];
            float4 m3 = mrow[j + 3], qv3 = qrow[j + 3];
            d0 += m0.x * qv0.x + m0.y * qv0.y + m0.z * qv0.z + m0.w * qv0.w;
            d1 += m1.x * qv1.x + m1.y * qv1.y + m1.z * qv1.z + m1.w * qv1.w;
            d2 += m2.x * qv2.x + m2.y * qv2.y + m2.z * qv2.z + m2.w * qv2.w;
            d3 += m3.x * qv3.x + m3.y * qv3.y + m3.z * qv3.z + m3.w * qv3.w;
        }
        float s = ((d0 + d1) + (d2 + d3) - g_hm2[idx]) * inv_s2;

        float mx = s;
#pragma unroll
        for (int off = 16; off; off >>= 1)
            mx = fmaxf(mx, __shfl_xor_sync(FULLMASK, mx, off));
        float e = __expf(s - mx);
        float se = e;
#pragma unroll
        for (int off = 16; off; off >>= 1)
            se += __shfl_xor_sync(FULLMASK, se, off);
        float wgt = e / se;

        myW[lane] = wgt;
        myI[lane] = idx;
        __syncwarp();

        // r_V: lane owns dims [4*lane, 4*lane+4)
        float4 acc = make_float4(0.f, 0.f, 0.f, 0.f);
#pragma unroll 4
        for (int k = 0; k < 32; k++) {
            float wk = myW[k];
            size_t row = (size_t)myI[k];
            float4 v = reinterpret_cast<const float4*>(V + row * 128)[lane];
            acc.x += wk * v.x; acc.y += wk * v.y;
            acc.z += wk * v.z; acc.w += wk * v.w;
        }

        // r_E (4 dims)
        float re = 0.f;
        if (lane < 4) {
            for (int k = 0; k < 32; k++)
                re += myW[k] * E[(size_t)myI[k] * 4 + lane];
        }

        // gate: sigmoid( x.W1 + rV.W2 + b + gpw * g_prior )
        const float4 wv = reinterpret_cast<const float4*>(Wg + 256)[lane];
        float tot = acc.x * wv.x + acc.y * wv.y + acc.z * wv.z + acc.w * wv.w;
        const float* xq = x + (size_t)qg2 * 256;
#pragma unroll
        for (int u = 0; u < 8; u++) {
            int t = lane + 32 * u;
            tot += xq[t] * Wg[t];
        }
#pragma unroll
        for (int off = 16; off; off >>= 1)
            tot += __shfl_xor_sync(FULLMASK, tot, off);

        reinterpret_cast<float4*>(out + RV_OFF + (size_t)qg2 * 128)[lane] = acc;
        if (lane < 4) out[RE_OFF + (size_t)qg2 * 4 + lane] = re;
        if (lane == 0) {
            float z = tot + bgate + gw * g_prior[qg2];
            out[G_OFF + qg2] = 1.f / (1.f + __expf(-z));
        }
        __syncwarp();
    }
}

extern "C" void kernel_launch(void* const* d_in, const int* in_sizes, int n_in,
                              void* d_out, int out_size) {
    (void)in_sizes; (void)n_in; (void)out_size;
    const float* x   = (const float*)d_in[0];
    const float* qt  = (const float*)d_in[1];
    const float* gp  = (const float*)d_in[2];
    const float* mu  = (const float*)d_in[3];
    const float* V   = (const float*)d_in[4];
    const float* E   = (const float*)d_in[5];
    const float* sg  = (const float*)d_in[6];
    const float* Wg  = (const float*)d_in[7];
    const float* Wb  = (const float*)d_in[8];
    const float* gw  = (const float*)d_in[9];

    prep_kernel<<<NC / 256, 256>>>(mu);

    const int smem_bytes = SMEM_FLOATS * 4;   // 98304
    cudaFuncSetAttribute(ma_kernel, cudaFuncAttributeMaxDynamicSharedMemorySize,
                         smem_bytes);
    ma_kernel<<<NQ / QT, 256, smem_bytes>>>(x, qt, gp, mu, V, E, sg, Wg, Wb, gw,
                                            (float*)d_out);
}

// round 7
// speedup vs baseline: 1.9005x; 1.0302x over previous
#include <cuda_runtime.h>
#include <cstdint>

// ---------------------------------------------------------------------------
// MemoryAttention R7: tf32 tensor-core GEMM (R6) + pipelined selection.
//   - double-buffered score tile: select(ch-1) runs inside iteration ch,
//     overlapped with GEMM(ch); ONE barrier per chunk (was two).
//   - selection steady state: 1 LDS.128 + 1 ballot per query-chunk.
//   - sQ aliased into sS0 (epilogue rescores from gmem) -> fits 2 CTAs/SM.
//   - epilogue rescores selected indices exactly in fp32 (outputs exact).
// ---------------------------------------------------------------------------

#define FULLMASK 0xffffffffu

static __device__ float g_hm2[32768];
static __device__ float g_mu_tf32[32768 * 64];   // tf32-rounded mu (8 MB)

constexpr int NQ  = 8192;
constexpr int NC  = 32768;
constexpr int DK  = 64;
constexpr int QT  = 32;       // queries per CTA
constexpr int CT  = 128;      // centers per chunk
constexpr int NCHUNK = NC / CT;   // 256
constexpr int MUS  = 68;      // mu smem row stride (floats)
constexpr int SSTR = 132;     // score row stride
constexpr int SBUF = QT * SSTR;   // 4224 floats per score buffer

constexpr int RV_OFF = 0;
constexpr int RE_OFF = NQ * 128;
constexpr int G_OFF  = RE_OFF + NQ * 4;

// smem layout (floats)
constexpr int OFF_MU  = 0;                        // 2*128*68 = 17408
constexpr int OFF_HM2 = OFF_MU + 2 * CT * MUS;    // 256
constexpr int OFF_S0  = OFF_HM2 + 2 * CT;         // 4224 (sQ aliases here)
constexpr int OFF_S1  = OFF_S0 + SBUF;            // 4224
constexpr int OFF_SCR = OFF_S1 + SBUF;            // 512
constexpr int SMEM_FLOATS = OFF_SCR + 8 * 64;     // 26624 floats = 106496 B

__device__ __forceinline__ uint32_t to_tf32(float f) {
    uint32_t u;
    asm("cvt.rna.tf32.f32 %0, %1;" : "=r"(u) : "f"(f));
    return u;
}

__global__ void prep_kernel(const float* __restrict__ mu) {
    int c = blockIdx.x * 256 + threadIdx.x;   // 128 x 256 = 32768 rows
    const float4* r = reinterpret_cast<const float4*>(mu) + (size_t)c * 16;
    float4* w = reinterpret_cast<float4*>(g_mu_tf32) + (size_t)c * 16;
    float s = 0.f;
#pragma unroll
    for (int j = 0; j < 16; j++) {
        float4 v = r[j];
        s += v.x * v.x + v.y * v.y + v.z * v.z + v.w * v.w;
        float4 t;
        t.x = __uint_as_float(to_tf32(v.x));
        t.y = __uint_as_float(to_tf32(v.y));
        t.z = __uint_as_float(to_tf32(v.z));
        t.w = __uint_as_float(to_tf32(v.w));
        w[j] = t;
    }
    g_hm2[c] = 0.5f * s;
}

// order-preserving float <-> uint
__device__ __forceinline__ unsigned fenc(float f) {
    unsigned u = __float_as_uint(f);
    return (u & 0x80000000u) ? ~u : (u | 0x80000000u);
}
__device__ __forceinline__ float fdec(unsigned u) {
    return (u & 0x80000000u) ? __uint_as_float(u & 0x7fffffffu)
                             : __uint_as_float(~u);
}
__device__ __forceinline__ unsigned redux_min_u32(unsigned v) {
    unsigned r;
    asm("redux.sync.min.u32 %0, %1, 0xffffffff;" : "=r"(r) : "r"(v));
    return r;
}

__device__ __forceinline__ void mma_tf32(float* d, const uint32_t* a,
                                         uint32_t b0, uint32_t b1) {
    asm("mma.sync.aligned.m16n8k8.row.col.f32.tf32.tf32.f32 "
        "{%0,%1,%2,%3}, {%4,%5,%6,%7}, {%8,%9}, {%0,%1,%2,%3};"
        : "+f"(d[0]), "+f"(d[1]), "+f"(d[2]), "+f"(d[3])
        : "r"(a[0]), "r"(a[1]), "r"(a[2]), "r"(a[3]), "r"(b0), "r"(b1));
}

__global__ __launch_bounds__(256, 2)
void ma_kernel(const float* __restrict__ x,
               const float* __restrict__ q_tilde,
               const float* __restrict__ g_prior,
               const float* __restrict__ mu,
               const float* __restrict__ V,
               const float* __restrict__ E,
               const float* __restrict__ sig,
               const float* __restrict__ Wg,
               const float* __restrict__ Wgb,
               const float* __restrict__ gpw,
               float* __restrict__ out) {
    extern __shared__ float sm[];
    float* sMu  = sm + OFF_MU;
    float* sHm2 = sm + OFF_HM2;
    float* sS   = sm + OFF_S0;     // two buffers: sS + buf*SBUF
    float* sQ   = sm + OFF_S0;     // alias: Q staged here only for A-frags
    float* sScr = sm + OFF_SCR;

    const int tid  = threadIdx.x;
    const int lane = tid & 31;
    const int wid  = tid >> 5;
    const int q0   = blockIdx.x * QT;

    // warp grid: wq in {0,1} (16 q-rows each), wc in {0..3} (32 centers each)
    const int wq = wid >> 2;
    const int wc = wid & 3;
    const int tr = lane >> 2;   // 0..7
    const int tc = lane & 3;    // 0..3

    const uint32_t smuA = (uint32_t)__cvta_generic_to_shared(sMu);
    const uint32_t shmA = (uint32_t)__cvta_generic_to_shared(sHm2);

    auto issue_chunk = [&](int chunk) {
        int buf = chunk & 1;
        uint32_t mdst = smuA + (uint32_t)(buf * (CT * MUS * 4));
        const float* src = g_mu_tf32 + (size_t)chunk * CT * DK;
#pragma unroll
        for (int j = 0; j < 8; j++) {
            int idx = tid + 256 * j;            // 128 rows x 16 float4
            int c = idx >> 4, kq = idx & 15;
            asm volatile("cp.async.cg.shared.global [%0], [%1], 16;\n"
                         :: "r"(mdst + (uint32_t)((c * MUS + kq * 4) * 4)),
                            "l"(src + c * DK + kq * 4));
        }
        if (tid < 32) {
            asm volatile("cp.async.cg.shared.global [%0], [%1], 16;\n"
                         :: "r"(shmA + (uint32_t)(buf * CT * 4 + tid * 16)),
                            "l"(g_hm2 + chunk * CT + tid * 4));
        }
        asm volatile("cp.async.commit_group;\n");
    };

    // ---- prologue: stage Q (aliased region), build A fragments ----
#pragma unroll
    for (int j = 0; j < 8; j++) {
        int idx = tid + 256 * j;
        int q = idx >> 6, k = idx & 63;
        sQ[q * MUS + k] = q_tilde[(size_t)(q0 + q) * DK + k];
    }
    issue_chunk(0);
    __syncthreads();   // sQ visible

    uint32_t af[8][4];
    {
        const float* qa = sQ + (16 * wq + tr) * MUS + tc;
#pragma unroll
        for (int kt = 0; kt < 8; kt++) {
            af[kt][0] = to_tf32(qa[8 * kt]);
            af[kt][1] = to_tf32(qa[8 * MUS + 8 * kt]);
            af[kt][2] = to_tf32(qa[8 * kt + 4]);
            af[kt][3] = to_tf32(qa[8 * MUS + 8 * kt + 4]);
        }
    }
    // NOTE: sQ is dead from here; first write to sS0 happens after the
    // first in-loop __syncthreads(), which orders it after all frag loads.

    // selection state: warp wid owns queries 4*wid + r
    unsigned cu[4]; int ci[4]; float thr[4]; unsigned thrU[4];
    const unsigned NEGINF_U = fenc(-INFINITY);
#pragma unroll
    for (int r = 0; r < 4; r++) {
        cu[r] = NEGINF_U; ci[r] = 0; thr[r] = -INFINITY; thrU[r] = NEGINF_U;
    }

    // deferred selection of one chunk's score tile (reads sbuf)
    auto select_chunk = [&](const float* sbuf, int base) {
#pragma unroll
        for (int r = 0; r < 4; r++) {
            const float* row = sbuf + (4 * wid + r) * SSTR;
            float4 f = *reinterpret_cast<const float4*>(row + 4 * lane);
            float lmax = fmaxf(fmaxf(f.x, f.y), fmaxf(f.z, f.w));
            unsigned m = __ballot_sync(FULLMASK, lmax > thr[r]);
            while (m) {
                int src = __ffs(m) - 1;
                m &= m - 1;
                float g0 = __shfl_sync(FULLMASK, f.x, src);
                float g1 = __shfl_sync(FULLMASK, f.y, src);
                float g2 = __shfl_sync(FULLMASK, f.z, src);
                float g3 = __shfl_sync(FULLMASK, f.w, src);
                int ib = base + 4 * src;
#pragma unroll
                for (int j = 0; j < 4; j++) {
                    float nv = (j == 0) ? g0 : (j == 1) ? g1 : (j == 2) ? g2 : g3;
                    if (nv > thr[r]) {
                        unsigned bl = __ballot_sync(FULLMASK, cu[r] == thrU[r]);
                        int ml = __ffs(bl) - 1;
                        if (lane == ml) { cu[r] = fenc(nv); ci[r] = ib + j; }
                        thrU[r] = redux_min_u32(cu[r]);
                        thr[r]  = fdec(thrU[r]);
                    }
                }
            }
        }
    };

    for (int ch = 0; ch < NCHUNK; ++ch) {
        asm volatile("cp.async.wait_group 0;\n");
        __syncthreads();   // orders: mu[ch&1] ready; stores(ch-1) complete;
                           // select(ch-2) complete (sS[ch&1] free);
                           // GEMM(ch-1) reads of mu[(ch+1)&1] done
        if (ch + 1 < NCHUNK) issue_chunk(ch + 1);

        const float* mb = sMu + (ch & 1) * (CT * MUS);
        const float* hb = sHm2 + (ch & 1) * CT;

        // ---- tensor-core GEMM: warp tile 16q x 32c ----
        float acc[4][4];
#pragma unroll
        for (int nt = 0; nt < 4; nt++)
#pragma unroll
            for (int j = 0; j < 4; j++) acc[nt][j] = 0.f;

        const float* bp = mb + (32 * wc + tr) * MUS + tc;
#pragma unroll
        for (int kt = 0; kt < 8; kt++) {
#pragma unroll
            for (int nt = 0; nt < 4; nt++) {
                uint32_t b0 = __float_as_uint(bp[(8 * nt) * MUS + 8 * kt]);
                uint32_t b1 = __float_as_uint(bp[(8 * nt) * MUS + 8 * kt + 4]);
                mma_tf32(acc[nt], af[kt], b0, b1);
            }
        }

        // ---- deferred selection of previous chunk (overlaps GEMM latency) ----
        if (ch > 0)
            select_chunk(sS + ((ch - 1) & 1) * SBUF, (ch - 1) * CT);

        // ---- scores s' = q.mu - 0.5||mu||^2 -> sS[ch&1] ----
        {
            float* sb = sS + (ch & 1) * SBUF;
            const float* hbase = hb + 32 * wc + 2 * tc;
            float* srow = sb + (16 * wq + tr) * SSTR + 32 * wc + 2 * tc;
#pragma unroll
            for (int nt = 0; nt < 4; nt++) {
                float2 h = *reinterpret_cast<const float2*>(hbase + 8 * nt);
                float2 lo, hi;
                lo.x = acc[nt][0] - h.x;  lo.y = acc[nt][1] - h.y;
                hi.x = acc[nt][2] - h.x;  hi.y = acc[nt][3] - h.y;
                *reinterpret_cast<float2*>(srow + 8 * nt) = lo;
                *reinterpret_cast<float2*>(srow + 8 * SSTR + 8 * nt) = hi;
            }
        }
    }

    // final chunk's selection
    __syncthreads();
    select_chunk(sS + ((NCHUNK - 1) & 1) * SBUF, (NCHUNK - 1) * CT);

    // publish top-32 indices per query into sS0 (select read sS1: disjoint)
    int* sTopI = reinterpret_cast<int*>(sS);
#pragma unroll
    for (int r = 0; r < 4; r++) {
        int q = 4 * wid + r;
        sTopI[q * 32 + lane] = ci[r];
    }
    __syncthreads();

    const float sigma  = sig[0];
    const float inv_s2 = 1.f / (sigma * sigma);
    const float bgate  = Wgb[0];
    const float gw     = gpw[0];

    float* myW = sScr + wid * 64;
    int*   myI = reinterpret_cast<int*>(myW + 32);

    // ---- epilogue: EXACT rescore + softmax + gathers + gate ----
#pragma unroll
    for (int round = 0; round < 4; ++round) {
        int q   = wid + 8 * round;
        int qg2 = q0 + q;

        int idx = sTopI[q * 32 + lane];

        // exact fp32 score: q . mu[idx] - 0.5||mu[idx]||^2  (q from gmem, L2-hot)
        const float4* mrow = reinterpret_cast<const float4*>(mu + (size_t)idx * DK);
        const float4* qrow = reinterpret_cast<const float4*>(q_tilde + (size_t)qg2 * DK);
        float d0 = 0.f, d1 = 0.f, d2 = 0.f, d3 = 0.f;
#pragma unroll
        for (int j = 0; j < 16; j += 4) {
            float4 m0 = mrow[j],     qv0 = qrow[j];
            float4 m1 = mrow[j + 1], qv1 = qrow[j + 1];
            float4 m2 = mrow[j + 2], qv2 = qrow[j + 2];
            float4 m3 = mrow[j + 3], qv3 = qrow[j + 3];
            d0 += m0.x * qv0.x + m0.y * qv0.y + m0.z * qv0.z + m0.w * qv0.w;
            d1 += m1.x * qv1.x + m1.y * qv1.y + m1.z * qv1.z + m1.w * qv1.w;
            d2 += m2.x * qv2.x + m2.y * qv2.y + m2.z * qv2.z + m2.w * qv2.w;
            d3 += m3.x * qv3.x + m3.y * qv3.y + m3.z * qv3.z + m3.w * qv3.w;
        }
        float s = ((d0 + d1) + (d2 + d3) - g_hm2[idx]) * inv_s2;

        float mx = s;
#pragma unroll
        for (int off = 16; off; off >>= 1)
            mx = fmaxf(mx, __shfl_xor_sync(FULLMASK, mx, off));
        float e = __expf(s - mx);
        float se = e;
#pragma unroll
        for (int off = 16; off; off >>= 1)
            se += __shfl_xor_sync(FULLMASK, se, off);
        float wgt = e / se;

        myW[lane] = wgt;
        myI[lane] = idx;
        __syncwarp();

        // r_V: lane owns dims [4*lane, 4*lane+4)
        float4 acc = make_float4(0.f, 0.f, 0.f, 0.f);
#pragma unroll 4
        for (int k = 0; k < 32; k++) {
            float wk = myW[k];
            size_t row = (size_t)myI[k];
            float4 v = reinterpret_cast<const float4*>(V + row * 128)[lane];
            acc.x += wk * v.x; acc.y += wk * v.y;
            acc.z += wk * v.z; acc.w += wk * v.w;
        }

        // r_E (4 dims)
        float re = 0.f;
        if (lane < 4) {
            for (int k = 0; k < 32; k++)
                re += myW[k] * E[(size_t)myI[k] * 4 + lane];
        }

        // gate: sigmoid( x.W1 + rV.W2 + b + gpw * g_prior )
        const float4 wv = reinterpret_cast<const float4*>(Wg + 256)[lane];
        float tot = acc.x * wv.x + acc.y * wv.y + acc.z * wv.z + acc.w * wv.w;
        const float* xq = x + (size_t)qg2 * 256;
#pragma unroll
        for (int u = 0; u < 8; u++) {
            int t = lane + 32 * u;
            tot += xq[t] * Wg[t];
        }
#pragma unroll
        for (int off = 16; off; off >>= 1)
            tot += __shfl_xor_sync(FULLMASK, tot, off);

        reinterpret_cast<float4*>(out + RV_OFF + (size_t)qg2 * 128)[lane] = acc;
        if (lane < 4) out[RE_OFF + (size_t)qg2 * 4 + lane] = re;
        if (lane == 0) {
            float z = tot + bgate + gw * g_prior[qg2];
            out[G_OFF + qg2] = 1.f / (1.f + __expf(-z));
        }
        __syncwarp();
    }
}

extern "C" void kernel_launch(void* const* d_in, const int* in_sizes, int n_in,
                              void* d_out, int out_size) {
    (void)in_sizes; (void)n_in; (void)out_size;
    const float* x   = (const float*)d_in[0];
    const float* qt  = (const float*)d_in[1];
    const float* gp  = (const float*)d_in[2];
    const float* mu  = (const float*)d_in[3];
    const float* V   = (const float*)d_in[4];
    const float* E   = (const float*)d_in[5];
    const float* sg  = (const float*)d_in[6];
    const float* Wg  = (const float*)d_in[7];
    const float* Wb  = (const float*)d_in[8];
    const float* gw  = (const float*)d_in[9];

    prep_kernel<<<NC / 256, 256>>>(mu);

    const int smem_bytes = SMEM_FLOATS * 4;   // 106496
    cudaFuncSetAttribute(ma_kernel, cudaFuncAttributeMaxDynamicSharedMemorySize,
                         smem_bytes);
    ma_kernel<<<NQ / QT, 256, smem_bytes>>>(x, qt, gp, mu, V, E, sg, Wg, Wb, gw,
                                            (float*)d_out);
}

// round 8
// speedup vs baseline: 2.0112x; 1.0583x over previous
#include <cuda_runtime.h>
#include <cstdint>

// ---------------------------------------------------------------------------
// MemoryAttention R8: R7 + ldmatrix B-fragment loads (4x fewer LSU instrs).
//   - B fragments via ldmatrix.m8n8.x4.b16: tf32 8x8 tile == 8x4 fp32 tile;
//     fragment reg m of lane l = M_m[l>>2][l&3] == B[n][k] exactly.
//   - 16 LDSM + 32 MMA per warp per chunk (was 64 LDS.32 + 32 MMA).
//   - selection fast path: one combined ballot across the warp's 4 queries.
//   - everything else identical to R7 (pipelined select, exact rescore).
// ---------------------------------------------------------------------------

#define FULLMASK 0xffffffffu

static __device__ float g_hm2[32768];
static __device__ float g_mu_tf32[32768 * 64];   // tf32-rounded mu (8 MB)

constexpr int NQ  = 8192;
constexpr int NC  = 32768;
constexpr int DK  = 64;
constexpr int QT  = 32;       // queries per CTA
constexpr int CT  = 128;      // centers per chunk
constexpr int NCHUNK = NC / CT;   // 256
constexpr int MUS  = 68;      // mu smem row stride (floats)
constexpr int SSTR = 132;     // score row stride
constexpr int SBUF = QT * SSTR;   // floats per score buffer

constexpr int RV_OFF = 0;
constexpr int RE_OFF = NQ * 128;
constexpr int G_OFF  = RE_OFF + NQ * 4;

// smem layout (floats)
constexpr int OFF_MU  = 0;                        // 2*128*68 = 17408
constexpr int OFF_HM2 = OFF_MU + 2 * CT * MUS;    // 256
constexpr int OFF_S0  = OFF_HM2 + 2 * CT;         // 4224 (sQ aliases here)
constexpr int OFF_S1  = OFF_S0 + SBUF;            // 4224
constexpr int OFF_SCR = OFF_S1 + SBUF;            // 512
constexpr int SMEM_FLOATS = OFF_SCR + 8 * 64;     // 26624 floats = 106496 B

__device__ __forceinline__ uint32_t to_tf32(float f) {
    uint32_t u;
    asm("cvt.rna.tf32.f32 %0, %1;" : "=r"(u) : "f"(f));
    return u;
}

__global__ void prep_kernel(const float* __restrict__ mu) {
    int c = blockIdx.x * 256 + threadIdx.x;   // 128 x 256 = 32768 rows
    const float4* r = reinterpret_cast<const float4*>(mu) + (size_t)c * 16;
    float4* w = reinterpret_cast<float4*>(g_mu_tf32) + (size_t)c * 16;
    float s = 0.f;
#pragma unroll
    for (int j = 0; j < 16; j++) {
        float4 v = r[j];
        s += v.x * v.x + v.y * v.y + v.z * v.z + v.w * v.w;
        float4 t;
        t.x = __uint_as_float(to_tf32(v.x));
        t.y = __uint_as_float(to_tf32(v.y));
        t.z = __uint_as_float(to_tf32(v.z));
        t.w = __uint_as_float(to_tf32(v.w));
        w[j] = t;
    }
    g_hm2[c] = 0.5f * s;
}

// order-preserving float <-> uint
__device__ __forceinline__ unsigned fenc(float f) {
    unsigned u = __float_as_uint(f);
    return (u & 0x80000000u) ? ~u : (u | 0x80000000u);
}
__device__ __forceinline__ float fdec(unsigned u) {
    return (u & 0x80000000u) ? __uint_as_float(u & 0x7fffffffu)
                             : __uint_as_float(~u);
}
__device__ __forceinline__ unsigned redux_min_u32(unsigned v) {
    unsigned r;
    asm("redux.sync.min.u32 %0, %1, 0xffffffff;" : "=r"(r) : "r"(v));
    return r;
}

__device__ __forceinline__ void mma_tf32(float* d, const uint32_t* a,
                                         uint32_t b0, uint32_t b1) {
    asm("mma.sync.aligned.m16n8k8.row.col.f32.tf32.tf32.f32 "
        "{%0,%1,%2,%3}, {%4,%5,%6,%7}, {%8,%9}, {%0,%1,%2,%3};"
        : "+f"(d[0]), "+f"(d[1]), "+f"(d[2]), "+f"(d[3])
        : "r"(a[0]), "r"(a[1]), "r"(a[2]), "r"(a[3]), "r"(b0), "r"(b1));
}

__device__ __forceinline__ void ldsm_x4(uint32_t addr, uint32_t& r0,
                                        uint32_t& r1, uint32_t& r2, uint32_t& r3) {
    asm volatile("ldmatrix.sync.aligned.m8n8.x4.shared.b16 {%0,%1,%2,%3}, [%4];"
                 : "=r"(r0), "=r"(r1), "=r"(r2), "=r"(r3) : "r"(addr));
}

__global__ __launch_bounds__(256, 2)
void ma_kernel(const float* __restrict__ x,
               const float* __restrict__ q_tilde,
               const float* __restrict__ g_prior,
               const float* __restrict__ mu,
               const float* __restrict__ V,
               const float* __restrict__ E,
               const float* __restrict__ sig,
               const float* __restrict__ Wg,
               const float* __restrict__ Wgb,
               const float* __restrict__ gpw,
               float* __restrict__ out) {
    extern __shared__ float sm[];
    float* sMu  = sm + OFF_MU;
    float* sHm2 = sm + OFF_HM2;
    float* sS   = sm + OFF_S0;     // two buffers: sS + buf*SBUF
    float* sQ   = sm + OFF_S0;     // alias: Q staged here only for A-frags
    float* sScr = sm + OFF_SCR;

    const int tid  = threadIdx.x;
    const int lane = tid & 31;
    const int wid  = tid >> 5;
    const int q0   = blockIdx.x * QT;

    // warp grid: wq in {0,1} (16 q-rows each), wc in {0..3} (32 centers each)
    const int wq = wid >> 2;
    const int wc = wid & 3;
    const int tr = lane >> 2;   // 0..7
    const int tc = lane & 3;    // 0..3

    const uint32_t smuA = (uint32_t)__cvta_generic_to_shared(sMu);
    const uint32_t shmA = (uint32_t)__cvta_generic_to_shared(sHm2);

    // ldmatrix lane address offsets (bytes) within a mu buffer:
    //   matrix pair ntp covers n-tiles {2ntp, 2ntp+1}; lane group l>>3 picks
    //   (matrix): m0 = rows 32wc+16ntp..+7, k lo; m1 = same rows, k hi(+4);
    //   m2/m3 = rows +8. Row stride = MUS floats, conflict-free (4r mod 32).
    const uint32_t boff0 = (uint32_t)(((32 * wc + ((lane >> 4) & 1) * 8 + (lane & 7)) * MUS
                                       + ((lane >> 3) & 1) * 4) * 4);
    const uint32_t boff1 = boff0 + (uint32_t)(16 * MUS * 4);

    auto issue_chunk = [&](int chunk) {
        int buf = chunk & 1;
        uint32_t mdst = smuA + (uint32_t)(buf * (CT * MUS * 4));
        const float* src = g_mu_tf32 + (size_t)chunk * CT * DK;
#pragma unroll
        for (int j = 0; j < 8; j++) {
            int idx = tid + 256 * j;            // 128 rows x 16 float4
            int c = idx >> 4, kq = idx & 15;
            asm volatile("cp.async.cg.shared.global [%0], [%1], 16;\n"
                         :: "r"(mdst + (uint32_t)((c * MUS + kq * 4) * 4)),
                            "l"(src + c * DK + kq * 4));
        }
        if (tid < 32) {
            asm volatile("cp.async.cg.shared.global [%0], [%1], 16;\n"
                         :: "r"(shmA + (uint32_t)(buf * CT * 4 + tid * 16)),
                            "l"(g_hm2 + chunk * CT + tid * 4));
        }
        asm volatile("cp.async.commit_group;\n");
    };

    // ---- prologue: stage Q (aliased region), build A fragments ----
#pragma unroll
    for (int j = 0; j < 8; j++) {
        int idx = tid + 256 * j;
        int q = idx >> 6, k = idx & 63;
        sQ[q * MUS + k] = q_tilde[(size_t)(q0 + q) * DK + k];
    }
    issue_chunk(0);
    __syncthreads();   // sQ visible

    uint32_t af[8][4];
    {
        const float* qa = sQ + (16 * wq + tr) * MUS + tc;
#pragma unroll
        for (int kt = 0; kt < 8; kt++) {
            af[kt][0] = to_tf32(qa[8 * kt]);
            af[kt][1] = to_tf32(qa[8 * MUS + 8 * kt]);
            af[kt][2] = to_tf32(qa[8 * kt + 4]);
            af[kt][3] = to_tf32(qa[8 * MUS + 8 * kt + 4]);
        }
    }
    // sQ dead from here; first sS0 write is after the first in-loop barrier.

    // selection state: warp wid owns queries 4*wid + r
    unsigned cu[4]; int ci[4]; float thr[4]; unsigned thrU[4];
    const unsigned NEGINF_U = fenc(-INFINITY);
#pragma unroll
    for (int r = 0; r < 4; r++) {
        cu[r] = NEGINF_U; ci[r] = 0; thr[r] = -INFINITY; thrU[r] = NEGINF_U;
    }

    // deferred selection of one chunk's score tile (reads sbuf)
    auto select_chunk = [&](const float* sbuf, int base) {
        float4 f[4]; float lmax[4];
#pragma unroll
        for (int r = 0; r < 4; r++) {
            const float* row = sbuf + (4 * wid + r) * SSTR;
            f[r] = *reinterpret_cast<const float4*>(row + 4 * lane);
            lmax[r] = fmaxf(fmaxf(f[r].x, f[r].y), fmaxf(f[r].z, f[r].w));
        }
        bool anyc = (lmax[0] > thr[0]) | (lmax[1] > thr[1]) |
                    (lmax[2] > thr[2]) | (lmax[3] > thr[3]);
        if (!__ballot_sync(FULLMASK, anyc)) return;
#pragma unroll
        for (int r = 0; r < 4; r++) {
            unsigned m = __ballot_sync(FULLMASK, lmax[r] > thr[r]);
            while (m) {
                int src = __ffs(m) - 1;
                m &= m - 1;
                float g0 = __shfl_sync(FULLMASK, f[r].x, src);
                float g1 = __shfl_sync(FULLMASK, f[r].y, src);
                float g2 = __shfl_sync(FULLMASK, f[r].z, src);
                float g3 = __shfl_sync(FULLMASK, f[r].w, src);
                int ib = base + 4 * src;
#pragma unroll
                for (int j = 0; j < 4; j++) {
                    float nv = (j == 0) ? g0 : (j == 1) ? g1 : (j == 2) ? g2 : g3;
                    if (nv > thr[r]) {
                        unsigned bl = __ballot_sync(FULLMASK, cu[r] == thrU[r]);
                        int ml = __ffs(bl) - 1;
                        if (lane == ml) { cu[r] = fenc(nv); ci[r] = ib + j; }
                        thrU[r] = redux_min_u32(cu[r]);
                        thr[r]  = fdec(thrU[r]);
                    }
                }
            }
        }
    };

    for (int ch = 0; ch < NCHUNK; ++ch) {
        asm volatile("cp.async.wait_group 0;\n");
        __syncthreads();   // mu[ch&1] ready; stores(ch-1) done; select(ch-2) done
        if (ch + 1 < NCHUNK) issue_chunk(ch + 1);

        const uint32_t bB = smuA + (uint32_t)((ch & 1) * (CT * MUS * 4));
        const float* hb = sHm2 + (ch & 1) * CT;

        // ---- tensor-core GEMM: warp tile 16q x 32c, B via ldmatrix ----
        float acc[4][4];
#pragma unroll
        for (int nt = 0; nt < 4; nt++)
#pragma unroll
            for (int j = 0; j < 4; j++) acc[nt][j] = 0.f;

        const uint32_t a0 = bB + boff0;
        const uint32_t a1 = bB + boff1;
#pragma unroll
        for (int kt = 0; kt < 8; kt++) {
            uint32_t r0, r1, r2, r3, s0, s1, s2, s3;
            ldsm_x4(a0 + kt * 32, r0, r1, r2, r3);
            ldsm_x4(a1 + kt * 32, s0, s1, s2, s3);
            mma_tf32(acc[0], af[kt], r0, r1);
            mma_tf32(acc[1], af[kt], r2, r3);
            mma_tf32(acc[2], af[kt], s0, s1);
            mma_tf32(acc[3], af[kt], s2, s3);
        }

        // ---- deferred selection of previous chunk (overlaps GEMM latency) ----
        if (ch > 0)
            select_chunk(sS + ((ch - 1) & 1) * SBUF, (ch - 1) * CT);

        // ---- scores s' = q.mu - 0.5||mu||^2 -> sS[ch&1] ----
        {
            float* sb = sS + (ch & 1) * SBUF;
            const float* hbase = hb + 32 * wc + 2 * tc;
            float* srow = sb + (16 * wq + tr) * SSTR + 32 * wc + 2 * tc;
#pragma unroll
            for (int nt = 0; nt < 4; nt++) {
                float2 h = *reinterpret_cast<const float2*>(hbase + 8 * nt);
                float2 lo, hi;
                lo.x = acc[nt][0] - h.x;  lo.y = acc[nt][1] - h.y;
                hi.x = acc[nt][2] - h.x;  hi.y = acc[nt][3] - h.y;
                *reinterpret_cast<float2*>(srow + 8 * nt) = lo;
                *reinterpret_cast<float2*>(srow + 8 * SSTR + 8 * nt) = hi;
            }
        }
    }

    // final chunk's selection
    __syncthreads();
    select_chunk(sS + ((NCHUNK - 1) & 1) * SBUF, (NCHUNK - 1) * CT);

    // publish top-32 indices per query into sS0 (final select read sS1)
    int* sTopI = reinterpret_cast<int*>(sS);
#pragma unroll
    for (int r = 0; r < 4; r++) {
        int q = 4 * wid + r;
        sTopI[q * 32 + lane] = ci[r];
    }
    __syncthreads();

    const float sigma  = sig[0];
    const float inv_s2 = 1.f / (sigma * sigma);
    const float bgate  = Wgb[0];
    const float gw     = gpw[0];

    float* myW = sScr + wid * 64;
    int*   myI = reinterpret_cast<int*>(myW + 32);

    // ---- epilogue: EXACT rescore + softmax + gathers + gate ----
#pragma unroll
    for (int round = 0; round < 4; ++round) {
        int q   = wid + 8 * round;
        int qg2 = q0 + q;

        int idx = sTopI[q * 32 + lane];

        // exact fp32 score: q . mu[idx] - 0.5||mu[idx]||^2
        const float4* mrow = reinterpret_cast<const float4*>(mu + (size_t)idx * DK);
        const float4* qrow = reinterpret_cast<const float4*>(q_tilde + (size_t)qg2 * DK);
        float d0 = 0.f, d1 = 0.f, d2 = 0.f, d3 = 0.f;
#pragma unroll
        for (int j = 0; j < 16; j += 4) {
            float4 m0 = mrow[j],     qv0 = qrow[j];
            float4 m1 = mrow[j + 1], qv1 = qrow[j + 1];
            float4 m2 = mrow[j + 2], qv2 = qrow[j + 2];
            float4 m3 = mrow[j + 3], qv3 = qrow[j + 3];
            d0 += m0.x * qv0.x + m0.y * qv0.y + m0.z * qv0.z + m0.w * qv0.w;
            d1 += m1.x * qv1.x + m1.y * qv1.y + m1.z * qv1.z + m1.w * qv1.w;
            d2 += m2.x * qv2.x + m2.y * qv2.y + m2.z * qv2.z + m2.w * qv2.w;
            d3 += m3.x * qv3.x + m3.y * qv3.y + m3.z * qv3.z + m3.w * qv3.w;
        }
        float s = ((d0 + d1) + (d2 + d3) - g_hm2[idx]) * inv_s2;

        float mx = s;
#pragma unroll
        for (int off = 16; off; off >>= 1)
            mx = fmaxf(mx, __shfl_xor_sync(FULLMASK, mx, off));
        float e = __expf(s - mx);
        float se = e;
#pragma unroll
        for (int off = 16; off; off >>= 1)
            se += __shfl_xor_sync(FULLMASK, se, off);
        float wgt = e / se;

        myW[lane] = wgt;
        myI[lane] = idx;
        __syncwarp();

        // r_V: lane owns dims [4*lane, 4*lane+4)
        float4 acc = make_float4(0.f, 0.f, 0.f, 0.f);
#pragma unroll 4
        for (int k = 0; k < 32; k++) {
            float wk = myW[k];
            size_t row = (size_t)myI[k];
            float4 v = reinterpret_cast<const float4*>(V + row * 128)[lane];
            acc.x += wk * v.x; acc.y += wk * v.y;
            acc.z += wk * v.z; acc.w += wk * v.w;
        }

        // r_E (4 dims)
        float re = 0.f;
        if (lane < 4) {
            for (int k = 0; k < 32; k++)
                re += myW[k] * E[(size_t)myI[k] * 4 + lane];
        }

        // gate: sigmoid( x.W1 + rV.W2 + b + gpw * g_prior )
        const float4 wv = reinterpret_cast<const float4*>(Wg + 256)[lane];
        float tot = acc.x * wv.x + acc.y * wv.y + acc.z * wv.z + acc.w * wv.w;
        const float* xq = x + (size_t)qg2 * 256;
#pragma unroll
        for (int u = 0; u < 8; u++) {
            int t = lane + 32 * u;
            tot += xq[t] * Wg[t];
        }
#pragma unroll
        for (int off = 16; off; off >>= 1)
            tot += __shfl_xor_sync(FULLMASK, tot, off);

        reinterpret_cast<float4*>(out + RV_OFF + (size_t)qg2 * 128)[lane] = acc;
        if (lane < 4) out[RE_OFF + (size_t)qg2 * 4 + lane] = re;
        if (lane == 0) {
            float z = tot + bgate + gw * g_prior[qg2];
            out[G_OFF + qg2] = 1.f / (1.f + __expf(-z));
        }
        __syncwarp();
    }
}

extern "C" void kernel_launch(void* const* d_in, const int* in_sizes, int n_in,
                              void* d_out, int out_size) {
    (void)in_sizes; (void)n_in; (void)out_size;
    const float* x   = (const float*)d_in[0];
    const float* qt  = (const float*)d_in[1];
    const float* gp  = (const float*)d_in[2];
    const float* mu  = (const float*)d_in[3];
    const float* V   = (const float*)d_in[4];
    const float* E   = (const float*)d_in[5];
    const float* sg  = (const float*)d_in[6];
    const float* Wg  = (const float*)d_in[7];
    const float* Wb  = (const float*)d_in[8];
    const float* gw  = (const float*)d_in[9];

    prep_kernel<<<NC / 256, 256>>>(mu);

    const int smem_bytes = SMEM_FLOATS * 4;   // 106496
    cudaFuncSetAttribute(ma_kernel, cudaFuncAttributeMaxDynamicSharedMemorySize,
                         smem_bytes);
    ma_kernel<<<NQ / QT, 256, smem_bytes>>>(x, qt, gp, mu, V, E, sg, Wg, Wb, gw,
                                            (float*)d_out);
}

// round 9
// speedup vs baseline: 2.5087x; 1.2474x over previous
#include <cuda_runtime.h>
#include <cstdint>

// ---------------------------------------------------------------------------
// MemoryAttention R9: R8 + TMA bulk prefetch.
//   - mu chunk prefetch: ONE cp.async.bulk (UBLKCP) + mbarrier per chunk,
//     replacing 2048 per-thread cp.async (LDGSTS) + address ALU.
//   - g_mu_pad: tf32 mu rows pre-padded to stride 68 with hm2 stored in the
//     padding (row[64] = 0.5||mu||^2), so one contiguous copy carries both.
//   - everything else identical to R8 (ldmatrix B-frags, pipelined select,
//     exact fp32 rescore epilogue).
// ---------------------------------------------------------------------------

#define FULLMASK 0xffffffffu

constexpr int NQ  = 8192;
constexpr int NC  = 32768;
constexpr int DK  = 64;
constexpr int QT  = 32;       // queries per CTA
constexpr int CT  = 128;      // centers per chunk
constexpr int NCHUNK = NC / CT;   // 256
constexpr int MUS  = 68;      // padded row stride (floats); row[64] = hm2
constexpr int SSTR = 132;     // score row stride
constexpr int SBUF = QT * SSTR;   // floats per score buffer
constexpr int BUFFLOATS = CT * MUS;          // 8704 floats per mu buffer
constexpr uint32_t BUFBYTES = BUFFLOATS * 4; // 34816 B (16B-multiple)

static __device__ float g_hm2[NC];
static __device__ float g_mu_pad[(size_t)NC * MUS];   // ~8.9 MB

constexpr int RV_OFF = 0;
constexpr int RE_OFF = NQ * 128;
constexpr int G_OFF  = RE_OFF + NQ * 4;

// smem layout (floats)
constexpr int OFF_MBAR = 0;                      // 2 x 8B mbarriers (8 floats)
constexpr int OFF_MU   = 8;                      // 2*8704 = 17408
constexpr int OFF_S0   = OFF_MU + 2 * BUFFLOATS; // 4224 (sQ aliases here)
constexpr int OFF_S1   = OFF_S0 + SBUF;          // 4224
constexpr int OFF_SCR  = OFF_S1 + SBUF;          // 512
constexpr int SMEM_FLOATS = OFF_SCR + 8 * 64;    // 26376 floats = 105504 B

__device__ __forceinline__ uint32_t to_tf32(float f) {
    uint32_t u;
    asm("cvt.rna.tf32.f32 %0, %1;" : "=r"(u) : "f"(f));
    return u;
}

__global__ void prep_kernel(const float* __restrict__ mu) {
    int c = blockIdx.x * 256 + threadIdx.x;   // 128 x 256 = 32768 rows
    const float4* r = reinterpret_cast<const float4*>(mu) + (size_t)c * 16;
    float* wrow = g_mu_pad + (size_t)c * MUS;
    float4* w = reinterpret_cast<float4*>(wrow);
    float s = 0.f;
#pragma unroll
    for (int j = 0; j < 16; j++) {
        float4 v = r[j];
        s += v.x * v.x + v.y * v.y + v.z * v.z + v.w * v.w;
        float4 t;
        t.x = __uint_as_float(to_tf32(v.x));
        t.y = __uint_as_float(to_tf32(v.y));
        t.z = __uint_as_float(to_tf32(v.z));
        t.w = __uint_as_float(to_tf32(v.w));
        w[j] = t;
    }
    wrow[64] = 0.5f * s;      // hm2 embedded in padding
    g_hm2[c] = 0.5f * s;      // for exact epilogue rescore
}

// order-preserving float <-> uint
__device__ __forceinline__ unsigned fenc(float f) {
    unsigned u = __float_as_uint(f);
    return (u & 0x80000000u) ? ~u : (u | 0x80000000u);
}
__device__ __forceinline__ float fdec(unsigned u) {
    return (u & 0x80000000u) ? __uint_as_float(u & 0x7fffffffu)
                             : __uint_as_float(~u);
}
__device__ __forceinline__ unsigned redux_min_u32(unsigned v) {
    unsigned r;
    asm("redux.sync.min.u32 %0, %1, 0xffffffff;" : "=r"(r) : "r"(v));
    return r;
}

__device__ __forceinline__ void mma_tf32(float* d, const uint32_t* a,
                                         uint32_t b0, uint32_t b1) {
    asm("mma.sync.aligned.m16n8k8.row.col.f32.tf32.tf32.f32 "
        "{%0,%1,%2,%3}, {%4,%5,%6,%7}, {%8,%9}, {%0,%1,%2,%3};"
        : "+f"(d[0]), "+f"(d[1]), "+f"(d[2]), "+f"(d[3])
        : "r"(a[0]), "r"(a[1]), "r"(a[2]), "r"(a[3]), "r"(b0), "r"(b1));
}

__device__ __forceinline__ void ldsm_x4(uint32_t addr, uint32_t& r0,
                                        uint32_t& r1, uint32_t& r2, uint32_t& r3) {
    asm volatile("ldmatrix.sync.aligned.m8n8.x4.shared.b16 {%0,%1,%2,%3}, [%4];"
                 : "=r"(r0), "=r"(r1), "=r"(r2), "=r"(r3) : "r"(addr));
}

__device__ __forceinline__ void mbar_init(uint32_t addr, uint32_t count) {
    asm volatile("mbarrier.init.shared.b64 [%0], %1;" :: "r"(addr), "r"(count)
                 : "memory");
}
__device__ __forceinline__ void mbar_expect_tx(uint32_t addr, uint32_t bytes) {
    asm volatile("mbarrier.arrive.expect_tx.shared.b64 _, [%0], %1;"
                 :: "r"(addr), "r"(bytes) : "memory");
}
__device__ __forceinline__ void mbar_wait(uint32_t addr, uint32_t parity) {
    asm volatile(
        "{\n\t"
        ".reg .pred P;\n"
        "W_%=:\n\t"
        "mbarrier.try_wait.parity.acquire.cta.shared::cta.b64 P, [%0], %1, 0x989680;\n\t"
        "@P bra D_%=;\n\t"
        "bra W_%=;\n"
        "D_%=:\n\t"
        "}"
        :: "r"(addr), "r"(parity) : "memory");
}
__device__ __forceinline__ void bulk_g2s(uint32_t dst, const void* src,
                                         uint32_t bytes, uint32_t mbar) {
    asm volatile(
        "cp.async.bulk.shared::cta.global.mbarrier::complete_tx::bytes "
        "[%0], [%1], %2, [%3];"
        :: "r"(dst), "l"(src), "r"(bytes), "r"(mbar) : "memory");
}

__global__ __launch_bounds__(256, 2)
void ma_kernel(const float* __restrict__ x,
               const float* __restrict__ q_tilde,
               const float* __restrict__ g_prior,
               const float* __restrict__ mu,
               const float* __restrict__ V,
               const float* __restrict__ E,
               const float* __restrict__ sig,
               const float* __restrict__ Wg,
               const float* __restrict__ Wgb,
               const float* __restrict__ gpw,
               float* __restrict__ out) {
    extern __shared__ float sm[];
    float* sMu  = sm + OFF_MU;
    float* sS   = sm + OFF_S0;     // two buffers: sS + buf*SBUF
    float* sQ   = sm + OFF_S0;     // alias: Q staged here only for A-frags
    float* sScr = sm + OFF_SCR;

    const int tid  = threadIdx.x;
    const int lane = tid & 31;
    const int wid  = tid >> 5;
    const int q0   = blockIdx.x * QT;

    // warp grid: wq in {0,1} (16 q-rows each), wc in {0..3} (32 centers each)
    const int wq = wid >> 2;
    const int wc = wid & 3;
    const int tr = lane >> 2;   // 0..7
    const int tc = lane & 3;    // 0..3

    const uint32_t smemBase = (uint32_t)__cvta_generic_to_shared(sm);
    const uint32_t mbarA = smemBase + OFF_MBAR * 4;       // 2 mbarriers
    const uint32_t smuA  = smemBase + OFF_MU * 4;

    // ldmatrix lane address offsets (bytes) within a mu buffer (as R8)
    const uint32_t boff0 = (uint32_t)(((32 * wc + ((lane >> 4) & 1) * 8 + (lane & 7)) * MUS
                                       + ((lane >> 3) & 1) * 4) * 4);
    const uint32_t boff1 = boff0 + (uint32_t)(16 * MUS * 4);

    auto issue_chunk = [&](int chunk) {
        if (tid == 0) {
            int buf = chunk & 1;
            uint32_t mb = mbarA + (uint32_t)(buf * 8);
            mbar_expect_tx(mb, BUFBYTES);
            bulk_g2s(smuA + (uint32_t)buf * BUFBYTES,
                     g_mu_pad + (size_t)chunk * BUFFLOATS, BUFBYTES, mb);
        }
    };

    // ---- prologue: stage Q (aliased region), init mbarriers ----
#pragma unroll
    for (int j = 0; j < 8; j++) {
        int idx = tid + 256 * j;
        int q = idx >> 6, k = idx & 63;
        sQ[q * MUS + k] = q_tilde[(size_t)(q0 + q) * DK + k];
    }
    if (tid == 0) {
        mbar_init(mbarA, 1);
        mbar_init(mbarA + 8, 1);
    }
    __syncthreads();   // sQ + mbarrier init visible
    issue_chunk(0);

    uint32_t af[8][4];
    {
        const float* qa = sQ + (16 * wq + tr) * MUS + tc;
#pragma unroll
        for (int kt = 0; kt < 8; kt++) {
            af[kt][0] = to_tf32(qa[8 * kt]);
            af[kt][1] = to_tf32(qa[8 * MUS + 8 * kt]);
            af[kt][2] = to_tf32(qa[8 * kt + 4]);
            af[kt][3] = to_tf32(qa[8 * MUS + 8 * kt + 4]);
        }
    }
    // sQ dead from here; first sS0 write is after the first in-loop barrier.

    // selection state: warp wid owns queries 4*wid + r
    unsigned cu[4]; int ci[4]; float thr[4]; unsigned thrU[4];
    const unsigned NEGINF_U = fenc(-INFINITY);
#pragma unroll
    for (int r = 0; r < 4; r++) {
        cu[r] = NEGINF_U; ci[r] = 0; thr[r] = -INFINITY; thrU[r] = NEGINF_U;
    }

    // deferred selection of one chunk's score tile (reads sbuf)
    auto select_chunk = [&](const float* sbuf, int base) {
        float4 f[4]; float lmax[4];
#pragma unroll
        for (int r = 0; r < 4; r++) {
            const float* row = sbuf + (4 * wid + r) * SSTR;
            f[r] = *reinterpret_cast<const float4*>(row + 4 * lane);
            lmax[r] = fmaxf(fmaxf(f[r].x, f[r].y), fmaxf(f[r].z, f[r].w));
        }
        bool anyc = (lmax[0] > thr[0]) | (lmax[1] > thr[1]) |
                    (lmax[2] > thr[2]) | (lmax[3] > thr[3]);
        if (!__ballot_sync(FULLMASK, anyc)) return;
#pragma unroll
        for (int r = 0; r < 4; r++) {
            unsigned m = __ballot_sync(FULLMASK, lmax[r] > thr[r]);
            while (m) {
                int src = __ffs(m) - 1;
                m &= m - 1;
                float g0 = __shfl_sync(FULLMASK, f[r].x, src);
                float g1 = __shfl_sync(FULLMASK, f[r].y, src);
                float g2 = __shfl_sync(FULLMASK, f[r].z, src);
                float g3 = __shfl_sync(FULLMASK, f[r].w, src);
                int ib = base + 4 * src;
#pragma unroll
                for (int j = 0; j < 4; j++) {
                    float nv = (j == 0) ? g0 : (j == 1) ? g1 : (j == 2) ? g2 : g3;
                    if (nv > thr[r]) {
                        unsigned bl = __ballot_sync(FULLMASK, cu[r] == thrU[r]);
                        int ml = __ffs(bl) - 1;
                        if (lane == ml) { cu[r] = fenc(nv); ci[r] = ib + j; }
                        thrU[r] = redux_min_u32(cu[r]);
                        thr[r]  = fdec(thrU[r]);
                    }
                }
            }
        }
    };

    for (int ch = 0; ch < NCHUNK; ++ch) {
        mbar_wait(mbarA + (uint32_t)((ch & 1) * 8), (ch >> 1) & 1);
        __syncthreads();   // buffer visible to all; stores(ch-1), select(ch-2),
                           // and GEMM(ch-1) reads of buffer (ch+1)&1 complete
        if (ch + 1 < NCHUNK) issue_chunk(ch + 1);

        const uint32_t bB = smuA + (uint32_t)((ch & 1)) * BUFBYTES;
        const float* mb = sMu + (ch & 1) * BUFFLOATS;

        // ---- tensor-core GEMM: warp tile 16q x 32c, B via ldmatrix ----
        float acc[4][4];
#pragma unroll
        for (int nt = 0; nt < 4; nt++)
#pragma unroll
            for (int j = 0; j < 4; j++) acc[nt][j] = 0.f;

        const uint32_t a0 = bB + boff0;
        const uint32_t a1 = bB + boff1;
#pragma unroll
        for (int kt = 0; kt < 8; kt++) {
            uint32_t r0, r1, r2, r3, s0, s1, s2, s3;
            ldsm_x4(a0 + kt * 32, r0, r1, r2, r3);
            ldsm_x4(a1 + kt * 32, s0, s1, s2, s3);
            mma_tf32(acc[0], af[kt], r0, r1);
            mma_tf32(acc[1], af[kt], r2, r3);
            mma_tf32(acc[2], af[kt], s0, s1);
            mma_tf32(acc[3], af[kt], s2, s3);
        }

        // ---- deferred selection of previous chunk (overlaps GEMM latency) ----
        if (ch > 0)
            select_chunk(sS + ((ch - 1) & 1) * SBUF, (ch - 1) * CT);

        // ---- scores s' = q.mu - hm2 -> sS[ch&1]; hm2 at row[64] ----
        {
            float* sb = sS + (ch & 1) * SBUF;
            const int n0 = 32 * wc + 2 * tc;
            float* srow = sb + (16 * wq + tr) * SSTR + n0;
#pragma unroll
            for (int nt = 0; nt < 4; nt++) {
                float hx = mb[(n0 + 8 * nt) * MUS + 64];
                float hy = mb[(n0 + 8 * nt + 1) * MUS + 64];
                float2 lo, hi;
                lo.x = acc[nt][0] - hx;  lo.y = acc[nt][1] - hy;
                hi.x = acc[nt][2] - hx;  hi.y = acc[nt][3] - hy;
                *reinterpret_cast<float2*>(srow + 8 * nt) = lo;
                *reinterpret_cast<float2*>(srow + 8 * SSTR + 8 * nt) = hi;
            }
        }
    }

    // final chunk's selection
    __syncthreads();
    select_chunk(sS + ((NCHUNK - 1) & 1) * SBUF, (NCHUNK - 1) * CT);

    // publish top-32 indices per query into sS0 (final select read sS1)
    int* sTopI = reinterpret_cast<int*>(sS);
#pragma unroll
    for (int r = 0; r < 4; r++) {
        int q = 4 * wid + r;
        sTopI[q * 32 + lane] = ci[r];
    }
    __syncthreads();

    const float sigma  = sig[0];
    const float inv_s2 = 1.f / (sigma * sigma);
    const float bgate  = Wgb[0];
    const float gw     = gpw[0];

    float* myW = sScr + wid * 64;
    int*   myI = reinterpret_cast<int*>(myW + 32);

    // ---- epilogue: EXACT rescore + softmax + gathers + gate ----
#pragma unroll
    for (int round = 0; round < 4; ++round) {
        int q   = wid + 8 * round;
        int qg2 = q0 + q;

        int idx = sTopI[q * 32 + lane];

        // exact fp32 score: q . mu[idx] - 0.5||mu[idx]||^2
        const float4* mrow = reinterpret_cast<const float4*>(mu + (size_t)idx * DK);
        const float4* qrow = reinterpret_cast<const float4*>(q_tilde + (size_t)qg2 * DK);
        float d0 = 0.f, d1 = 0.f, d2 = 0.f, d3 = 0.f;
#pragma unroll
        for (int j = 0; j < 16; j += 4) {
            float4 m0 = mrow[j],     qv0 = qrow[j];
            float4 m1 = mrow[j + 1], qv1 = qrow[j + 1];
            float4 m2 = mrow[j + 2], qv2 = qrow[j + 2];
            float4 m3 = mrow[j + 3], qv3 = qrow[j + 3];
            d0 += m0.x * qv0.x + m0.y * qv0.y + m0.z * qv0.z + m0.w * qv0.w;
            d1 += m1.x * qv1.x + m1.y * qv1.y + m1.z * qv1.z + m1.w * qv1.w;
            d2 += m2.x * qv2.x + m2.y * qv2.y + m2.z * qv2.z + m2.w * qv2.w;
            d3 += m3.x * qv3.x + m3.y * qv3.y + m3.z * qv3.z + m3.w * qv3.w;
        }
        float s = ((d0 + d1) + (d2 + d3) - g_hm2[idx]) * inv_s2;

        float mx = s;
#pragma unroll
        for (int off = 16; off; off >>= 1)
            mx = fmaxf(mx, __shfl_xor_sync(FULLMASK, mx, off));
        float e = __expf(s - mx);
        float se = e;
#pragma unroll
        for (int off = 16; off; off >>= 1)
            se += __shfl_xor_sync(FULLMASK, se, off);
        float wgt = e / se;

        myW[lane] = wgt;
        myI[lane] = idx;
        __syncwarp();

        // r_V: lane owns dims [4*lane, 4*lane+4)
        float4 acc = make_float4(0.f, 0.f, 0.f, 0.f);
#pragma unroll 4
        for (int k = 0; k < 32; k++) {
            float wk = myW[k];
            size_t row = (size_t)myI[k];
            float4 v = reinterpret_cast<const float4*>(V + row * 128)[lane];
            acc.x += wk * v.x; acc.y += wk * v.y;
            acc.z += wk * v.z; acc.w += wk * v.w;
        }

        // r_E (4 dims)
        float re = 0.f;
        if (lane < 4) {
            for (int k = 0; k < 32; k++)
                re += myW[k] * E[(size_t)myI[k] * 4 + lane];
        }

        // gate: sigmoid( x.W1 + rV.W2 + b + gpw * g_prior )
        const float4 wv = reinterpret_cast<const float4*>(Wg + 256)[lane];
        float tot = acc.x * wv.x + acc.y * wv.y + acc.z * wv.z + acc.w * wv.w;
        const float* xq = x + (size_t)qg2 * 256;
#pragma unroll
        for (int u = 0; u < 8; u++) {
            int t = lane + 32 * u;
            tot += xq[t] * Wg[t];
        }
#pragma unroll
        for (int off = 16; off; off >>= 1)
            tot += __shfl_xor_sync(FULLMASK, tot, off);

        reinterpret_cast<float4*>(out + RV_OFF + (size_t)qg2 * 128)[lane] = acc;
        if (lane < 4) out[RE_OFF + (size_t)qg2 * 4 + lane] = re;
        if (lane == 0) {
            float z = tot + bgate + gw * g_prior[qg2];
            out[G_OFF + qg2] = 1.f / (1.f + __expf(-z));
        }
        __syncwarp();
    }
}

extern "C" void kernel_launch(void* const* d_in, const int* in_sizes, int n_in,
                              void* d_out, int out_size) {
    (void)in_sizes; (void)n_in; (void)out_size;
    const float* x   = (const float*)d_in[0];
    const float* qt  = (const float*)d_in[1];
    const float* gp  = (const float*)d_in[2];
    const float* mu  = (const float*)d_in[3];
    const float* V   = (const float*)d_in[4];
    const float* E   = (const float*)d_in[5];
    const float* sg  = (const float*)d_in[6];
    const float* Wg  = (const float*)d_in[7];
    const float* Wb  = (const float*)d_in[8];
    const float* gw  = (const float*)d_in[9];

    prep_kernel<<<NC / 256, 256>>>(mu);

    const int smem_bytes = SMEM_FLOATS * 4;   // 105504
    cudaFuncSetAttribute(ma_kernel, cudaFuncAttributeMaxDynamicSharedMemorySize,
                         smem_bytes);
    ma_kernel<<<NQ / QT, 256, smem_bytes>>>(x, qt, gp, mu, V, E, sg, Wg, Wb, gw,
                                            (float*)d_out);
}

// round 10
// speedup vs baseline: 2.5516x; 1.0171x over previous
#include <cuda_runtime.h>
#include <cstdint>

// ---------------------------------------------------------------------------
// MemoryAttention R10: R9 + vectorized score path.
//   - score columns permuted p(n) = (n&7)*16 + (n>>3) and XOR-swizzled
//     W(p) = p ^ ((p>>4 & 7) << 2): score stores 4x STS.128 (was 8x STS.64),
//     hm2 loads 2x LDS.128 (was 8x LDS.32), all bank-conflict-free.
//   - TMA blob per chunk: [hm2 permuted+swizzled: 128 f][mu tf32: 128x68 f].
//   - select reads float4 at 4*(lane^ (lane>>2)); index decode on insert only.
//   - otherwise identical to R9 (TMA bulk, ldmatrix, pipelined select,
//     exact fp32 rescore epilogue).
// ---------------------------------------------------------------------------

#define FULLMASK 0xffffffffu

constexpr int NQ  = 8192;
constexpr int NC  = 32768;
constexpr int DK  = 64;
constexpr int QT  = 32;       // queries per CTA
constexpr int CT  = 128;      // centers per chunk
constexpr int NCHUNK = NC / CT;   // 256
constexpr int MUS  = 68;      // mu row stride (floats) inside blob
constexpr int SSTR = 132;     // score row stride
constexpr int SBUF = QT * SSTR;   // floats per score buffer
constexpr int BUFFLOATS = CT + CT * MUS;      // 128 hm2 + 8704 mu = 8832
constexpr uint32_t BUFBYTES = BUFFLOATS * 4;  // 35328 B (16B-multiple)

static __device__ float g_hm2[NC];
static __device__ float g_blob[(size_t)NCHUNK * BUFFLOATS];   // ~9 MB

constexpr int RV_OFF = 0;
constexpr int RE_OFF = NQ * 128;
constexpr int G_OFF  = RE_OFF + NQ * 4;

// smem layout (floats)
constexpr int OFF_MBAR = 0;                        // 2 x 8B mbarriers
constexpr int OFF_BLOB = 8;                        // 2*8832 = 17664
constexpr int OFF_S0   = OFF_BLOB + 2 * BUFFLOATS; // 4224 (sQ aliases here)
constexpr int OFF_S1   = OFF_S0 + SBUF;            // 4224
constexpr int OFF_SCR  = OFF_S1 + SBUF;            // 512
constexpr int SMEM_FLOATS = OFF_SCR + 8 * 64;      // 26632 fl = 106528 B

__device__ __forceinline__ uint32_t to_tf32(float f) {
    uint32_t u;
    asm("cvt.rna.tf32.f32 %0, %1;" : "=r"(u) : "f"(f));
    return u;
}

__global__ void prep_kernel(const float* __restrict__ mu) {
    int c = blockIdx.x * 256 + threadIdx.x;   // 128 x 256 = 32768 rows
    const float4* r = reinterpret_cast<const float4*>(mu) + (size_t)c * 16;
    int n = c & 127;
    float* blob = g_blob + (size_t)(c >> 7) * BUFFLOATS;
    float4* w = reinterpret_cast<float4*>(blob + CT + n * MUS);
    float s = 0.f;
#pragma unroll
    for (int j = 0; j < 16; j++) {
        float4 v = r[j];
        s += v.x * v.x + v.y * v.y + v.z * v.z + v.w * v.w;
        float4 t;
        t.x = __uint_as_float(to_tf32(v.x));
        t.y = __uint_as_float(to_tf32(v.y));
        t.z = __uint_as_float(to_tf32(v.z));
        t.w = __uint_as_float(to_tf32(v.w));
        w[j] = t;
    }
    // hm2 in permuted + swizzled order at blob start
    int p  = (n & 7) * 16 + (n >> 3);
    int ws = p ^ (((p >> 4) & 7) << 2);
    blob[ws] = 0.5f * s;
    g_hm2[c] = 0.5f * s;      // exact epilogue rescore
}

// order-preserving float <-> uint
__device__ __forceinline__ unsigned fenc(float f) {
    unsigned u = __float_as_uint(f);
    return (u & 0x80000000u) ? ~u : (u | 0x80000000u);
}
__device__ __forceinline__ float fdec(unsigned u) {
    return (u & 0x80000000u) ? __uint_as_float(u & 0x7fffffffu)
                             : __uint_as_float(~u);
}
__device__ __forceinline__ unsigned redux_min_u32(unsigned v) {
    unsigned r;
    asm("redux.sync.min.u32 %0, %1, 0xffffffff;" : "=r"(r) : "r"(v));
    return r;
}

__device__ __forceinline__ void mma_tf32(float* d, const uint32_t* a,
                                         uint32_t b0, uint32_t b1) {
    asm("mma.sync.aligned.m16n8k8.row.col.f32.tf32.tf32.f32 "
        "{%0,%1,%2,%3}, {%4,%5,%6,%7}, {%8,%9}, {%0,%1,%2,%3};"
        : "+f"(d[0]), "+f"(d[1]), "+f"(d[2]), "+f"(d[3])
        : "r"(a[0]), "r"(a[1]), "r"(a[2]), "r"(a[3]), "r"(b0), "r"(b1));
}

__device__ __forceinline__ void ldsm_x4(uint32_t addr, uint32_t& r0,
                                        uint32_t& r1, uint32_t& r2, uint32_t& r3) {
    asm volatile("ldmatrix.sync.aligned.m8n8.x4.shared.b16 {%0,%1,%2,%3}, [%4];"
                 : "=r"(r0), "=r"(r1), "=r"(r2), "=r"(r3) : "r"(addr));
}

__device__ __forceinline__ void mbar_init(uint32_t addr, uint32_t count) {
    asm volatile("mbarrier.init.shared.b64 [%0], %1;" :: "r"(addr), "r"(count)
                 : "memory");
}
__device__ __forceinline__ void mbar_expect_tx(uint32_t addr, uint32_t bytes) {
    asm volatile("mbarrier.arrive.expect_tx.shared.b64 _, [%0], %1;"
                 :: "r"(addr), "r"(bytes) : "memory");
}
__device__ __forceinline__ void mbar_wait(uint32_t addr, uint32_t parity) {
    asm volatile(
        "{\n\t"
        ".reg .pred P;\n"
        "W_%=:\n\t"
        "mbarrier.try_wait.parity.acquire.cta.shared::cta.b64 P, [%0], %1, 0x989680;\n\t"
        "@P bra D_%=;\n\t"
        "bra W_%=;\n"
        "D_%=:\n\t"
        "}"
        :: "r"(addr), "r"(parity) : "memory");
}
__device__ __forceinline__ void bulk_g2s(uint32_t dst, const void* src,
                                         uint32_t bytes, uint32_t mbar) {
    asm volatile(
        "cp.async.bulk.shared::cta.global.mbarrier::complete_tx::bytes "
        "[%0], [%1], %2, [%3];"
        :: "r"(dst), "l"(src), "r"(bytes), "r"(mbar) : "memory");
}

__global__ __launch_bounds__(256, 2)
void ma_kernel(const float* __restrict__ x,
               const float* __restrict__ q_tilde,
               const float* __restrict__ g_prior,
               const float* __restrict__ mu,
               const float* __restrict__ V,
               const float* __restrict__ E,
               const float* __restrict__ sig,
               const float* __restrict__ Wg,
               const float* __restrict__ Wgb,
               const float* __restrict__ gpw,
               float* __restrict__ out) {
    extern __shared__ float sm[];
    float* sBlob = sm + OFF_BLOB;
    float* sS    = sm + OFF_S0;     // two buffers: sS + buf*SBUF
    float* sQ    = sm + OFF_S0;     // alias: Q staged here only for A-frags
    float* sScr  = sm + OFF_SCR;

    const int tid  = threadIdx.x;
    const int lane = tid & 31;
    const int wid  = tid >> 5;
    const int q0   = blockIdx.x * QT;

    // warp grid: wq in {0,1} (16 q-rows each), wc in {0..3} (32 centers each)
    const int wq = wid >> 2;
    const int wc = wid & 3;
    const int tr = lane >> 2;   // 0..7
    const int tc = lane & 3;    // 0..3

    const uint32_t smemBase = (uint32_t)__cvta_generic_to_shared(sm);
    const uint32_t mbarA  = smemBase + OFF_MBAR * 4;
    const uint32_t sblobA = smemBase + OFF_BLOB * 4;

    // ldmatrix lane address offsets (bytes) within a blob's mu section
    const uint32_t boff0 = (uint32_t)(CT * 4) +   // skip hm2 section
        (uint32_t)(((32 * wc + ((lane >> 4) & 1) * 8 + (lane & 7)) * MUS
                    + ((lane >> 3) & 1) * 4) * 4);
    const uint32_t boff1 = boff0 + (uint32_t)(16 * MUS * 4);

    // swizzled word offsets for this thread's hm2 / score float4s
    const int blk0 = 2 * tc, blk1 = 2 * tc + 1;
    const int w0 = (blk0 * 16 + 4 * wc) ^ (blk0 << 2);
    const int w1 = (blk1 * 16 + 4 * wc) ^ (blk1 << 2);

    auto issue_chunk = [&](int chunk) {
        if (tid == 0) {
            int buf = chunk & 1;
            uint32_t mb = mbarA + (uint32_t)(buf * 8);
            mbar_expect_tx(mb, BUFBYTES);
            bulk_g2s(sblobA + (uint32_t)buf * BUFBYTES,
                     g_blob + (size_t)chunk * BUFFLOATS, BUFBYTES, mb);
        }
    };

    // ---- prologue: stage Q (aliased region), init mbarriers ----
#pragma unroll
    for (int j = 0; j < 8; j++) {
        int idx = tid + 256 * j;
        int q = idx >> 6, k = idx & 63;
        sQ[q * MUS + k] = q_tilde[(size_t)(q0 + q) * DK + k];
    }
    if (tid == 0) {
        mbar_init(mbarA, 1);
        mbar_init(mbarA + 8, 1);
    }
    __syncthreads();   // sQ + mbarrier init visible
    issue_chunk(0);

    uint32_t af[8][4];
    {
        const float* qa = sQ + (16 * wq + tr) * MUS + tc;
#pragma unroll
        for (int kt = 0; kt < 8; kt++) {
            af[kt][0] = to_tf32(qa[8 * kt]);
            af[kt][1] = to_tf32(qa[8 * MUS + 8 * kt]);
            af[kt][2] = to_tf32(qa[8 * kt + 4]);
            af[kt][3] = to_tf32(qa[8 * MUS + 8 * kt + 4]);
        }
    }
    // sQ dead from here; first sS0 write is after the first in-loop barrier.

    // selection state: warp wid owns queries 4*wid + r
    unsigned cu[4]; int ci[4]; float thr[4]; unsigned thrU[4];
    const unsigned NEGINF_U = fenc(-INFINITY);
#pragma unroll
    for (int r = 0; r < 4; r++) {
        cu[r] = NEGINF_U; ci[r] = 0; thr[r] = -INFINITY; thrU[r] = NEGINF_U;
    }

    const int selw = 4 * (lane ^ (lane >> 2));   // swizzled select load offset

    // deferred selection of one chunk's score tile (reads sbuf)
    // lane's float4 = permuted positions 4*lane..+3; element j ->
    //   center index = base + 32*(lane&3) + 8*j + (lane>>2)
    auto select_chunk = [&](const float* sbuf, int base) {
        float4 f[4]; float lmax[4];
#pragma unroll
        for (int r = 0; r < 4; r++) {
            const float* row = sbuf + (4 * wid + r) * SSTR;
            f[r] = *reinterpret_cast<const float4*>(row + selw);
            lmax[r] = fmaxf(fmaxf(f[r].x, f[r].y), fmaxf(f[r].z, f[r].w));
        }
        bool anyc = (lmax[0] > thr[0]) | (lmax[1] > thr[1]) |
                    (lmax[2] > thr[2]) | (lmax[3] > thr[3]);
        if (!__ballot_sync(FULLMASK, anyc)) return;
#pragma unroll
        for (int r = 0; r < 4; r++) {
            unsigned m = __ballot_sync(FULLMASK, lmax[r] > thr[r]);
            while (m) {
                int src = __ffs(m) - 1;
                m &= m - 1;
                float g0 = __shfl_sync(FULLMASK, f[r].x, src);
                float g1 = __shfl_sync(FULLMASK, f[r].y, src);
                float g2 = __shfl_sync(FULLMASK, f[r].z, src);
                float g3 = __shfl_sync(FULLMASK, f[r].w, src);
                int ib = base + 32 * (src & 3) + (src >> 2);
#pragma unroll
                for (int j = 0; j < 4; j++) {
                    float nv = (j == 0) ? g0 : (j == 1) ? g1 : (j == 2) ? g2 : g3;
                    if (nv > thr[r]) {
                        unsigned bl = __ballot_sync(FULLMASK, cu[r] == thrU[r]);
                        int ml = __ffs(bl) - 1;
                        if (lane == ml) { cu[r] = fenc(nv); ci[r] = ib + 8 * j; }
                        thrU[r] = redux_min_u32(cu[r]);
                        thr[r]  = fdec(thrU[r]);
                    }
                }
            }
        }
    };

    for (int ch = 0; ch < NCHUNK; ++ch) {
        mbar_wait(mbarA + (uint32_t)((ch & 1) * 8), (ch >> 1) & 1);
        __syncthreads();   // buffer visible; stores(ch-1), select(ch-2) done
        if (ch + 1 < NCHUNK) issue_chunk(ch + 1);

        const uint32_t bufB = sblobA + (uint32_t)(ch & 1) * BUFBYTES;
        const float* hbp = sBlob + (ch & 1) * BUFFLOATS;   // hm2 section

        // ---- tensor-core GEMM: warp tile 16q x 32c, B via ldmatrix ----
        float acc[4][4];
#pragma unroll
        for (int nt = 0; nt < 4; nt++)
#pragma unroll
            for (int j = 0; j < 4; j++) acc[nt][j] = 0.f;

        const uint32_t a0 = bufB + boff0;
        const uint32_t a1 = bufB + boff1;
#pragma unroll
        for (int kt = 0; kt < 8; kt++) {
            uint32_t r0, r1, r2, r3, s0, s1, s2, s3;
            ldsm_x4(a0 + kt * 32, r0, r1, r2, r3);
            ldsm_x4(a1 + kt * 32, s0, s1, s2, s3);
            mma_tf32(acc[0], af[kt], r0, r1);
            mma_tf32(acc[1], af[kt], r2, r3);
            mma_tf32(acc[2], af[kt], s0, s1);
            mma_tf32(acc[3], af[kt], s2, s3);
        }

        // ---- deferred selection of previous chunk (overlaps GEMM latency) ----
        if (ch > 0)
            select_chunk(sS + ((ch - 1) & 1) * SBUF, (ch - 1) * CT);

        // ---- scores -> sS[ch&1], permuted+swizzled, 4x STS.128 ----
        {
            float* sb = sS + (ch & 1) * SBUF;
            float4 h0 = *reinterpret_cast<const float4*>(hbp + w0);
            float4 h1 = *reinterpret_cast<const float4*>(hbp + w1);
            float* r0 = sb + (16 * wq + tr) * SSTR;
            float* r1 = r0 + 8 * SSTR;
            float4 v;
            v.x = acc[0][0] - h0.x; v.y = acc[1][0] - h0.y;
            v.z = acc[2][0] - h0.z; v.w = acc[3][0] - h0.w;
            *reinterpret_cast<float4*>(r0 + w0) = v;
            v.x = acc[0][1] - h1.x; v.y = acc[1][1] - h1.y;
            v.z = acc[2][1] - h1.z; v.w = acc[3][1] - h1.w;
            *reinterpret_cast<float4*>(r0 + w1) = v;
            v.x = acc[0][2] - h0.x; v.y = acc[1][2] - h0.y;
            v.z = acc[2][2] - h0.z; v.w = acc[3][2] - h0.w;
            *reinterpret_cast<float4*>(r1 + w0) = v;
            v.x = acc[0][3] - h1.x; v.y = acc[1][3] - h1.y;
            v.z = acc[2][3] - h1.z; v.w = acc[3][3] - h1.w;
            *reinterpret_cast<float4*>(r1 + w1) = v;
        }
    }

    // final chunk's selection
    __syncthreads();
    select_chunk(sS + ((NCHUNK - 1) & 1) * SBUF, (NCHUNK - 1) * CT);

    // publish top-32 indices per query into sS0 (final select read sS1)
    int* sTopI = reinterpret_cast<int*>(sS);
#pragma unroll
    for (int r = 0; r < 4; r++) {
        int q = 4 * wid + r;
        sTopI[q * 32 + lane] = ci[r];
    }
    __syncthreads();

    const float sigma  = sig[0];
    const float inv_s2 = 1.f / (sigma * sigma);
    const float bgate  = Wgb[0];
    const float gw     = gpw[0];

    float* myW = sScr + wid * 64;
    int*   myI = reinterpret_cast<int*>(myW + 32);

    // ---- epilogue: EXACT rescore + softmax + gathers + gate ----
#pragma unroll
    for (int round = 0; round < 4; ++round) {
        int q   = wid + 8 * round;
        int qg2 = q0 + q;

        int idx = sTopI[q * 32 + lane];

        // exact fp32 score: q . mu[idx] - 0.5||mu[idx]||^2
        const float4* mrow = reinterpret_cast<const float4*>(mu + (size_t)idx * DK);
        const float4* qrow = reinterpret_cast<const float4*>(q_tilde + (size_t)qg2 * DK);
        float d0 = 0.f, d1 = 0.f, d2 = 0.f, d3 = 0.f;
#pragma unroll
        for (int j = 0; j < 16; j += 4) {
            float4 m0 = mrow[j],     qv0 = qrow[j];
            float4 m1 = mrow[j + 1], qv1 = qrow[j + 1];
            float4 m2 = mrow[j + 2], qv2 = qrow[j + 2];
            float4 m3 = mrow[j + 3], qv3 = qrow[j + 3];
            d0 += m0.x * qv0.x + m0.y * qv0.y + m0.z * qv0.z + m0.w * qv0.w;
            d1 += m1.x * qv1.x + m1.y * qv1.y + m1.z * qv1.z + m1.w * qv1.w;
            d2 += m2.x * qv2.x + m2.y * qv2.y + m2.z * qv2.z + m2.w * qv2.w;
            d3 += m3.x * qv3.x + m3.y * qv3.y + m3.z * qv3.z + m3.w * qv3.w;
        }
        float s = ((d0 + d1) + (d2 + d3) - g_hm2[idx]) * inv_s2;

        float mx = s;
#pragma unroll
        for (int off = 16; off; off >>= 1)
            mx = fmaxf(mx, __shfl_xor_sync(FULLMASK, mx, off));
        float e = __expf(s - mx);
        float se = e;
#pragma unroll
        for (int off = 16; off; off >>= 1)
            se += __shfl_xor_sync(FULLMASK, se, off);
        float wgt = e / se;

        myW[lane] = wgt;
        myI[lane] = idx;
        __syncwarp();

        // r_V: lane owns dims [4*lane, 4*lane+4)
        float4 acc = make_float4(0.f, 0.f, 0.f, 0.f);
#pragma unroll 4
        for (int k = 0; k < 32; k++) {
            float wk = myW[k];
            size_t row = (size_t)myI[k];
            float4 v = reinterpret_cast<const float4*>(V + row * 128)[lane];
            acc.x += wk * v.x; acc.y += wk * v.y;
            acc.z += wk * v.z; acc.w += wk * v.w;
        }

        // r_E (4 dims)
        float re = 0.f;
        if (lane < 4) {
            for (int k = 0; k < 32; k++)
                re += myW[k] * E[(size_t)myI[k] * 4 + lane];
        }

        // gate: sigmoid( x.W1 + rV.W2 + b + gpw * g_prior )
        const float4 wv = reinterpret_cast<const float4*>(Wg + 256)[lane];
        float tot = acc.x * wv.x + acc.y * wv.y + acc.z * wv.z + acc.w * wv.w;
        const float* xq = x + (size_t)qg2 * 256;
#pragma unroll
        for (int u = 0; u < 8; u++) {
            int t = lane + 32 * u;
            tot += xq[t] * Wg[t];
        }
#pragma unroll
        for (int off = 16; off; off >>= 1)
            tot += __shfl_xor_sync(FULLMASK, tot, off);

        reinterpret_cast<float4*>(out + RV_OFF + (size_t)qg2 * 128)[lane] = acc;
        if (lane < 4) out[RE_OFF + (size_t)qg2 * 4 + lane] = re;
        if (lane == 0) {
            float z = tot + bgate + gw * g_prior[qg2];
            out[G_OFF + qg2] = 1.f / (1.f + __expf(-z));
        }
        __syncwarp();
    }
}

extern "C" void kernel_launch(void* const* d_in, const int* in_sizes, int n_in,
                              void* d_out, int out_size) {
    (void)in_sizes; (void)n_in; (void)out_size;
    const float* x   = (const float*)d_in[0];
    const float* qt  = (const float*)d_in[1];
    const float* gp  = (const float*)d_in[2];
    const float* mu  = (const float*)d_in[3];
    const float* V   = (const float*)d_in[4];
    const float* E   = (const float*)d_in[5];
    const float* sg  = (const float*)d_in[6];
    const float* Wg  = (const float*)d_in[7];
    const float* Wb  = (const float*)d_in[8];
    const float* gw  = (const float*)d_in[9];

    prep_kernel<<<NC / 256, 256>>>(mu);

    const int smem_bytes = SMEM_FLOATS * 4;   // 106528
    cudaFuncSetAttribute(ma_kernel, cudaFuncAttributeMaxDynamicSharedMemorySize,
                         smem_bytes);
    ma_kernel<<<NQ / QT, 256, smem_bytes>>>(x, qt, gp, mu, V, E, sg, Wg, Wb, gw,
                                            (float*)d_out);
}